// round 14
// baseline (speedup 1.0000x reference)
#include <cuda_runtime.h>
#include <math.h>
#include <stdint.h>

// Dims: B=8 S=32 P=64 D=256 H=1024 K=1024 OBS=64 CTX=4 NH=4 dh=64

#define M1 1048576LL
#define OFF_TOK   (0LL)
#define OFF_QKV   (4*M1)
#define OFF_KV    (OFF_QKV)
#define OFF_QB1   (OFF_QKV + 32*M1)
#define OFF_ATTN  (52*M1)
#define OFF_XC    (68*M1)
#define OFF_BUF   (84*M1)
#define OFF_H     (100*M1)
#define OFF_DOT   (OFF_H)
#define OFF_CUR   (164*M1)
#define OFF_U     (168*M1)
#define OFF_CT    (172*M1)
#define OFF_BASE  (176*M1)
#define OFF_WS    (176*M1 + 65536)
#define OFF_CC    (176*M1 + 131072)
#define OFF_QKVB  (176*M1 + 133120)
#define OFF_QKVP  (176*M1 + 329728)
#define OFF_N1    (176*M1 + 378880)
#define OFF_M2    (OFF_N1 + 1*65536)
#define OFF_M3    (OFF_N1 + 2*65536)
#define OFF_M4    (OFF_N1 + 3*65536)
#define OFF_M5    (OFF_N1 + 4*65536)
#define OFF_M6    (OFF_N1 + 5*65536)
#define OFF_M7    (OFF_N1 + 6*65536)
#define OFF_M8    (OFF_N1 + 7*65536)
#define OFF_RD    (OFF_N1 + 8*65536)     // per-row best dist (16384)
// decoder scratch in fresh (non-aliased) space so it can run concurrently from t=0
#define OFF_DH1   (186*M1)
#define OFF_DH2   (187*M1)
#define OFF_LUT   (188*M1)

__device__ float g_arena[198000000];   // ~792 MB
__device__ int   g_idx[16384];

// ================= 3xTF32 tensor-core GEMM (round-6 engine, verbatim) =================
__device__ __forceinline__ uint32_t f2tf32(float x) {
    uint32_t r; asm("cvt.rna.tf32.f32 %0, %1;" : "=r"(r) : "f"(x)); return r;
}
__device__ __forceinline__ void mma_tf32(float* c, const uint32_t* a, uint32_t b0, uint32_t b1) {
    asm volatile("mma.sync.aligned.m16n8k8.row.col.f32.tf32.tf32.f32 "
        "{%0,%1,%2,%3}, {%4,%5,%6,%7}, {%8,%9}, {%0,%1,%2,%3};"
        : "+f"(c[0]), "+f"(c[1]), "+f"(c[2]), "+f"(c[3])
        : "r"(a[0]), "r"(a[1]), "r"(a[2]), "r"(a[3]), "r"(b0), "r"(b1));
}
__device__ __forceinline__ void cvt_store8(uint32_t (*H)[136], uint32_t (*L)[136],
                                           int r, float4 v0, float4 v1)
{
    float f[8] = {v0.x,v0.y,v0.z,v0.w,v1.x,v1.y,v1.z,v1.w};
#pragma unroll
    for (int k = 0; k < 8; k++) {
        uint32_t hi = f2tf32(f[k]);
        float lo = f[k] - __uint_as_float(hi);
        H[k][r] = hi;
        L[k][r] = f2tf32(lo);
    }
}

// epi: 0 = bias(+relu), 1 = accumulate into C, 2 = add D
__global__ __launch_bounds__(128) void mma_gemm(
    const float* __restrict__ Aext, long long aOff, int lda, long long aBatch,
    const float* __restrict__ Bext, long long bOff, int ldb,
    const float* __restrict__ biasExt,
    long long cOff, int ldc, long long cBatch,
    long long dOff,
    int M, int N, int K, int epi, float alpha, int relu)
{
    const float* A = (Aext ? Aext : (g_arena + aOff)) + (size_t)blockIdx.z * aBatch;
    const float* B = Bext ? Bext : (g_arena + bOff);
    float* C = g_arena + cOff + (size_t)blockIdx.z * cBatch;
    const float* D = g_arena + dOff + (size_t)blockIdx.z * cBatch;
    __shared__ uint32_t AsH[2][8][136], AsL[2][8][136], BsH[2][8][136], BsL[2][8][136];
    int tid = threadIdx.x, lane = tid & 31, wid = tid >> 5;
    int m0 = blockIdx.y * 128, n0 = blockIdx.x * 128;
    int wm = (wid & 1) * 64, wn = (wid >> 1) * 64;
    const float4 z4 = make_float4(0.f,0.f,0.f,0.f);

    int arow = m0 + tid, brow = n0 + tid;
    const float* Ab = A + (size_t)arow * lda;
    const float* Bb = B + (size_t)brow * ldb;
    bool am = arow < M, bm = brow < N;

    float4 a0,a1,b0,b1;
    a0 = am ? *(const float4*)Ab     : z4;
    a1 = am ? *(const float4*)(Ab+4) : z4;
    b0 = bm ? *(const float4*)Bb     : z4;
    b1 = bm ? *(const float4*)(Bb+4) : z4;
    cvt_store8(AsH[0], AsL[0], tid, a0, a1);
    cvt_store8(BsH[0], BsL[0], tid, b0, b1);
    __syncthreads();

    float acc[4][8][4];
#pragma unroll
    for (int i=0;i<4;i++)
#pragma unroll
        for (int j=0;j<8;j++)
#pragma unroll
            for (int q=0;q<4;q++) acc[i][j][q]=0.f;

    int ak = lane & 3, aq = lane >> 2;
    int nkt = K >> 3;
    for (int kt = 0; kt < nkt; kt++) {
        int buf = kt & 1;
        bool pf = (kt+1) < nkt;
        if (pf) {
            int k0 = (kt+1) << 3;
            a0 = am ? *(const float4*)(Ab+k0)   : z4;
            a1 = am ? *(const float4*)(Ab+k0+4) : z4;
            b0 = bm ? *(const float4*)(Bb+k0)   : z4;
            b1 = bm ? *(const float4*)(Bb+k0+4) : z4;
        }
        uint32_t aH[4][4], aL[4][4];
#pragma unroll
        for (int mi = 0; mi < 4; mi++) {
            int row = wm + mi*16 + aq;
            aH[mi][0]=AsH[buf][ak][row];   aH[mi][1]=AsH[buf][ak][row+8];
            aH[mi][2]=AsH[buf][ak+4][row]; aH[mi][3]=AsH[buf][ak+4][row+8];
            aL[mi][0]=AsL[buf][ak][row];   aL[mi][1]=AsL[buf][ak][row+8];
            aL[mi][2]=AsL[buf][ak+4][row]; aL[mi][3]=AsL[buf][ak+4][row+8];
        }
#pragma unroll
        for (int ni = 0; ni < 8; ni++) {
            int col = wn + ni*8 + aq;
            uint32_t bH0=BsH[buf][ak][col], bH1=BsH[buf][ak+4][col];
            uint32_t bL0=BsL[buf][ak][col], bL1=BsL[buf][ak+4][col];
#pragma unroll
            for (int mi = 0; mi < 4; mi++) {
                mma_tf32(acc[mi][ni], aH[mi], bH0, bH1);
                mma_tf32(acc[mi][ni], aL[mi], bH0, bH1);
                mma_tf32(acc[mi][ni], aH[mi], bL0, bL1);
            }
        }
        if (pf) {
            cvt_store8(AsH[buf^1], AsL[buf^1], tid, a0, a1);
            cvt_store8(BsH[buf^1], BsL[buf^1], tid, b0, b1);
            __syncthreads();
        }
    }
#pragma unroll
    for (int mi = 0; mi < 4; mi++) {
        int r0 = m0 + wm + mi*16 + aq;
#pragma unroll
        for (int ni = 0; ni < 8; ni++) {
            int c0 = n0 + wn + ni*8 + 2*ak;
            if (c0 >= N) continue;
            float v0 = alpha*acc[mi][ni][0], v1 = alpha*acc[mi][ni][1];
            float v2 = alpha*acc[mi][ni][2], v3 = alpha*acc[mi][ni][3];
            if (epi == 0) {
                float bb0 = biasExt ? biasExt[c0]   : 0.f;
                float bb1 = biasExt ? biasExt[c0+1] : 0.f;
                v0+=bb0; v1+=bb1; v2+=bb0; v3+=bb1;
                if (relu) { v0=fmaxf(v0,0.f); v1=fmaxf(v1,0.f); v2=fmaxf(v2,0.f); v3=fmaxf(v3,0.f); }
            } else if (epi == 1) {
                if (r0 < M)   { float2 c = *(float2*)(C + (size_t)r0*ldc + c0);     v0+=c.x; v1+=c.y; }
                if (r0+8 < M) { float2 c = *(float2*)(C + (size_t)(r0+8)*ldc + c0); v2+=c.x; v3+=c.y; }
            } else {
                if (r0 < M)   { float2 d = *(const float2*)(D + (size_t)r0*ldc + c0);     v0+=d.x; v1+=d.y; }
                if (r0+8 < M) { float2 d = *(const float2*)(D + (size_t)(r0+8)*ldc + c0); v2+=d.x; v3+=d.y; }
            }
            if (r0 < M)   *(float2*)(C + (size_t)r0*ldc + c0)     = make_float2(v0,v1);
            if (r0+8 < M) *(float2*)(C + (size_t)(r0+8)*ldc + c0) = make_float2(v2,v3);
        }
    }
}

// ---------------- tok_pre = base[bs] + pos_embed[p] ----------------
__global__ void tok_kernel(const float* __restrict__ pe)
{
    int e = blockIdx.x * 256 + threadIdx.x;
    int d = e & 255, r = e >> 8;
    int bs = r >> 6, p = r & 63;
    g_arena[OFF_TOK + e] = g_arena[OFF_BASE + bs*256 + d] + pe[p*256 + d];
}

// ---------------- self-attention; qkv from qkvb[bs]+qkvp[p] ----------------
__global__ __launch_bounds__(256) void sa_attn()
{
    float* out = g_arena + OFF_ATTN;
    int h  = blockIdx.x & 3;
    int bs = blockIdx.x >> 2;
    __shared__ float Qs[64][65], Ks[64][65], Vs[64][65];
    __shared__ float Ps[8][64];
    int t = threadIdx.x;
    const float* qb = g_arena + OFF_QKVB + bs*768 + h*64;
    const float* qp = g_arena + OFF_QKVP + h*64;
    for (int i = t; i < 4096; i += 256) {
        int rr = i >> 6, cc = i & 63;
        const float* pr = qp + rr*768 + cc;
        Qs[rr][cc] = pr[0]   + qb[cc];
        Ks[rr][cc] = pr[256] + qb[256+cc];
        Vs[rr][cc] = pr[512] + qb[512+cc];
    }
    __syncthreads();
    int w = t >> 5, lane = t & 31;
    for (int qi = w*8; qi < w*8+8; qi++) {
        float s0 = 0.f, s1 = 0.f;
#pragma unroll 8
        for (int d = 0; d < 64; d++) {
            float q = Qs[qi][d];
            s0 = fmaf(q, Ks[lane][d], s0);
            s1 = fmaf(q, Ks[lane+32][d], s1);
        }
        s0 *= 0.125f; s1 *= 0.125f;
        float mx = fmaxf(s0, s1);
#pragma unroll
        for (int o = 16; o; o >>= 1) mx = fmaxf(mx, __shfl_xor_sync(0xffffffffu, mx, o));
        float e0 = expf(s0 - mx), e1 = expf(s1 - mx);
        float sum = e0 + e1;
#pragma unroll
        for (int o = 16; o; o >>= 1) sum += __shfl_xor_sync(0xffffffffu, sum, o);
        float inv = 1.f / sum;
        Ps[w][lane] = e0 * inv; Ps[w][lane+32] = e1 * inv;
        __syncwarp();
        float o0 = 0.f, o1 = 0.f;
#pragma unroll 8
        for (int k = 0; k < 64; k++) {
            float p = Ps[w][k];
            o0 = fmaf(p, Vs[k][lane], o0);
            o1 = fmaf(p, Vs[k][lane+32], o1);
        }
        size_t ob = (size_t)(bs*64 + qi) * 256 + h*64;
        out[ob + lane] = o0;
        out[ob + lane + 32] = o1;
        __syncwarp();
    }
}

// ---------------- LN(x + r); rs==-2: residual = windowed tok gather ----------------
__global__ __launch_bounds__(256) void ln_kernel(long long xOff, int xs,
                                                 long long rOff, int rs,
                                                 const float* __restrict__ g, const float* __restrict__ b,
                                                 long long oOff, int os)
{
    int row = blockIdx.x, t = threadIdx.x;
    int w = t >> 5, lane = t & 31;
    float rres;
    if (rs == -2) {
        int j = row & 3, p = (row >> 2) & 63, s = (row >> 8) & 31, bb = row >> 13;
        int sp = s + j - 3;
        rres = (sp >= 0) ? g_arena[OFF_TOK + ((size_t)((bb*32 + sp)*64 + p))*256 + t] : 0.f;
    } else {
        rres = g_arena[rOff + (size_t)row*rs + t];
    }
    float v = g_arena[xOff + (size_t)row*xs + t] + rres;
    __shared__ float red[8];
    float s = v;
#pragma unroll
    for (int o = 16; o; o >>= 1) s += __shfl_xor_sync(0xffffffffu, s, o);
    if (lane == 0) red[w] = s;
    __syncthreads();
    float mean = (red[0]+red[1]+red[2]+red[3]+red[4]+red[5]+red[6]+red[7]) * (1.f/256.f);
    float dv = v - mean;
    s = dv*dv;
#pragma unroll
    for (int o = 16; o; o >>= 1) s += __shfl_xor_sync(0xffffffffu, s, o);
    __syncthreads();
    if (lane == 0) red[w] = s;
    __syncthreads();
    float var = (red[0]+red[1]+red[2]+red[3]+red[4]+red[5]+red[6]+red[7]) * (1.f/256.f);
    g_arena[oOff + (size_t)row*os + t] = dv * rsqrtf(var + 1e-5f) * g[t] + b[t];
}

// ---------------- ctx layer-0 attention (gather from per-token qkv) ----------------
__global__ __launch_bounds__(256) void ctx_attn0(const float* __restrict__ cqkv_b)
{
    float* out = g_arena + OFF_ATTN;
    const float* qt = g_arena + OFF_QKV;
    int wg = blockIdx.x * 8 + (threadIdx.x >> 5);
    int lane = threadIdx.x & 31;
    int seq = wg >> 2, h = wg & 3;
    int s = (seq >> 6) & 31;
    const float* bq = cqkv_b + h*64 + lane*2;
    float2 q[4], k[4], v[4];
#pragma unroll
    for (int j = 0; j < 4; j++) {
        if (s + j - 3 >= 0) {
            const float* row = qt + (size_t)(seq + (j-3)*64)*768 + h*64 + lane*2;
            q[j] = *(const float2*)row;
            k[j] = *(const float2*)(row + 256);
            v[j] = *(const float2*)(row + 512);
        } else {
            q[j] = *(const float2*)bq;
            k[j] = *(const float2*)(bq + 256);
            v[j] = *(const float2*)(bq + 512);
        }
    }
    float sc[4][4];
#pragma unroll
    for (int j = 0; j < 4; j++)
#pragma unroll
        for (int kk = 0; kk < 4; kk++)
            sc[j][kk] = q[j].x*k[kk].x + q[j].y*k[kk].y;
#pragma unroll
    for (int o = 16; o; o >>= 1)
#pragma unroll
        for (int j = 0; j < 4; j++)
#pragma unroll
            for (int kk = 0; kk < 4; kk++)
                sc[j][kk] += __shfl_xor_sync(0xffffffffu, sc[j][kk], o);
    float p[4][4];
#pragma unroll
    for (int j = 0; j < 4; j++) {
        float mx = -1e30f;
#pragma unroll
        for (int kk = 0; kk < 4; kk++) { sc[j][kk] *= 0.125f; mx = fmaxf(mx, sc[j][kk]); }
        float sum = 0.f;
#pragma unroll
        for (int kk = 0; kk < 4; kk++) { p[j][kk] = expf(sc[j][kk] - mx); sum += p[j][kk]; }
        float inv = 1.f / sum;
#pragma unroll
        for (int kk = 0; kk < 4; kk++) p[j][kk] *= inv;
    }
#pragma unroll
    for (int j = 0; j < 4; j++) {
        float2 o2 = make_float2(0.f, 0.f);
#pragma unroll
        for (int kk = 0; kk < 4; kk++) { o2.x = fmaf(p[j][kk], v[kk].x, o2.x); o2.y = fmaf(p[j][kk], v[kk].y, o2.y); }
        *(float2*)(out + ((size_t)seq*4 + j)*256 + h*64 + lane*2) = o2;
    }
}

// ---------------- ctx layer-1 attention (Q at j=3 only) ----------------
__global__ __launch_bounds__(256) void ctx_attn1()
{
    int wg = blockIdx.x * 8 + (threadIdx.x >> 5);
    int lane = threadIdx.x & 31;
    int seq = wg >> 2, h = wg & 3;
    float2 q = *(const float2*)(g_arena + OFF_QB1 + (size_t)seq*256 + h*64 + lane*2);
    float2 k[4], v[4];
#pragma unroll
    for (int j = 0; j < 4; j++) {
        const float* r = g_arena + OFF_KV + (size_t)(seq*4 + j)*512 + h*64 + lane*2;
        k[j] = *(const float2*)r;
        v[j] = *(const float2*)(r + 256);
    }
    float sc[4];
#pragma unroll
    for (int kk = 0; kk < 4; kk++) sc[kk] = q.x*k[kk].x + q.y*k[kk].y;
#pragma unroll
    for (int o = 16; o; o >>= 1)
#pragma unroll
        for (int kk = 0; kk < 4; kk++)
            sc[kk] += __shfl_xor_sync(0xffffffffu, sc[kk], o);
    float mx = -1e30f;
#pragma unroll
    for (int kk = 0; kk < 4; kk++) { sc[kk] *= 0.125f; mx = fmaxf(mx, sc[kk]); }
    float sum = 0.f; float p[4];
#pragma unroll
    for (int kk = 0; kk < 4; kk++) { p[kk] = expf(sc[kk] - mx); sum += p[kk]; }
    float inv = 1.f / sum;
    float2 o2 = make_float2(0.f, 0.f);
#pragma unroll
    for (int kk = 0; kk < 4; kk++) { o2.x = fmaf(p[kk]*inv, v[kk].x, o2.x); o2.y = fmaf(p[kk]*inv, v[kk].y, o2.y); }
    *(float2*)(g_arena + OFF_CUR + (size_t)seq*256 + h*64 + lane*2) = o2;
}

// ---------------- delta helpers ----------------
__global__ void wsum_kernel(const float* __restrict__ dw)
{
    int e = blockIdx.x * 256 + threadIdx.x;
    int d = e >> 8, k = e & 255;
    g_arena[OFF_WS + e] = dw[d*512 + k] + dw[d*512 + 256 + k];
}
// write cur[b][0] rows into BOTH u[b][0] and ct[b][0]
__global__ void copy_s0_both()
{
    int e = blockIdx.x * 256 + threadIdx.x;   // 131072
    int d = e & 255, p = (e >> 8) & 63, b = e >> 14;
    size_t off = ((size_t)(b*2048 + p))*256 + d;
    float v = g_arena[OFF_CUR + off];
    g_arena[OFF_U  + off] = v;
    g_arena[OFF_CT + off] = v;
}
// copy u group1 (z2, final ct[1]) into ct group1
__global__ void copy_grp1()
{
    int e = blockIdx.x * 256 + threadIdx.x;   // 524288
    int b = e >> 16, l = e & 65535;
    size_t off = (size_t)b * (2048*256) + 65536 + l;
    g_arena[OFF_CT + off] = g_arena[OFF_U + off];
}
__global__ void transpose_w2(const float* __restrict__ dw)
{
    int n = blockIdx.x, k = threadIdx.x;
    g_arena[OFF_N1 + (size_t)n*256 + k] = dw[(size_t)k*512 + 256 + n];
}

// ---------------- VQ ----------------
__global__ void cc_kernel(const float* __restrict__ cb)
{
    int row = blockIdx.x, t = threadIdx.x;
    float v = cb[row*256 + t];
    __shared__ float red[256];
    red[t] = v*v; __syncthreads();
    for (int o = 128; o; o >>= 1) { if (t < o) red[t] += red[t+o]; __syncthreads(); }
    if (t == 0) g_arena[OFF_CC + row] = red[0];
}
__global__ __launch_bounds__(256) void argmin_kernel()
{
    int row = blockIdx.x, t = threadIdx.x;
    float x = g_arena[OFF_CT + (size_t)row*256 + t];
    __shared__ float red[256];
    red[t] = x*x; __syncthreads();
    for (int o = 128; o; o >>= 1) { if (t < o) red[t] += red[t+o]; __syncthreads(); }
    float xx = red[0];
    __syncthreads();
    const float* dot = g_arena + OFF_DOT + (size_t)row*1024;
    float best = 3.4e38f; int bi = 0;
    for (int j = t; j < 1024; j += 256) {
        float dist = xx - 2.f*dot[j] + g_arena[OFF_CC + j];
        if (dist < best) { best = dist; bi = j; }
    }
    __shared__ float rv[256];
    __shared__ int   ri[256];
    rv[t] = best; ri[t] = bi; __syncthreads();
    for (int o = 128; o; o >>= 1) {
        if (t < o) {
            float v2 = rv[t+o]; int i2 = ri[t+o];
            if (v2 < rv[t] || (v2 == rv[t] && i2 < ri[t])) { rv[t] = v2; ri[t] = i2; }
        }
        __syncthreads();
    }
    if (t == 0) {
        g_idx[row] = ri[0];
        g_arena[OFF_RD + row] = rv[0];   // = sum((ct-q)^2) for this row
    }
}

// ---------------- output writers ----------------
__global__ void recon_kernel(float* __restrict__ out)
{
    int e = blockIdx.x * 256 + threadIdx.x;
    out[e] = g_arena[OFF_LUT + g_idx[e >> 6]*64 + (e & 63)];
}
__global__ void idx_kernel(float* __restrict__ out)
{
    int r = blockIdx.x * 256 + threadIdx.x;
    out[1048576 + r] = (float)g_idx[r];
}
// losses from per-row best dists (deterministic fixed-order sum)
__global__ void finalize_kernel(float* __restrict__ out)
{
    int t = threadIdx.x;
    float acc = 0.f;
    for (int k = 0; k < 64; k++)
        acc += g_arena[OFF_RD + t + 256*k];
    __shared__ float red[256];
    red[t] = acc; __syncthreads();
    for (int o = 128; o; o >>= 1) { if (t < o) red[t] += red[t+o]; __syncthreads(); }
    if (t == 0) {
        float mse = red[0] / 4194304.f;
        out[1064960] = 0.25f * mse;
        out[1064961] = mse;
        out[1064962] = 1.25f * mse;
    }
}

#define GEMM(grid, Aext,aOff,lda,aB, Bext,bOff,ldb, bias, cOff,ldc,cB, dOff, M,N,K, epi,alpha,relu) \
    mma_gemm<<<grid,128>>>(Aext,aOff,lda,aB, Bext,bOff,ldb, bias, cOff,ldc,cB, dOff, M,N,K, epi,alpha,relu)
#define GEMMS(st, grid, Aext,aOff,lda,aB, Bext,bOff,ldb, bias, cOff,ldc,cB, dOff, M,N,K, epi,alpha,relu) \
    mma_gemm<<<grid,128,0,st>>>(Aext,aOff,lda,aB, Bext,bOff,ldb, bias, cOff,ldc,cB, dOff, M,N,K, epi,alpha,relu)

// ---------------- orchestration ----------------
extern "C" void kernel_launch(void* const* d_in, const int* in_sizes, int n_in,
                              void* d_out, int out_size)
{
    const float* obs      = (const float*)d_in[0];
    const float* patch_w  = (const float*)d_in[2];
    const float* patch_b  = (const float*)d_in[3];
    const float* pos      = (const float*)d_in[4];
    const float* sa_qkv_w = (const float*)d_in[5];
    const float* sa_qkv_b = (const float*)d_in[6];
    const float* sa_out_w = (const float*)d_in[7];
    const float* sa_out_b = (const float*)d_in[8];
    const float* sa_ln_g  = (const float*)d_in[9];
    const float* sa_ln_b  = (const float*)d_in[10];
    const float* cqkv_w   = (const float*)d_in[11];
    const float* cqkv_b   = (const float*)d_in[12];
    const float* cout_w   = (const float*)d_in[13];
    const float* cout_b   = (const float*)d_in[14];
    const float* cff1_w   = (const float*)d_in[15];
    const float* cff1_b   = (const float*)d_in[16];
    const float* cff2_w   = (const float*)d_in[17];
    const float* cff2_b   = (const float*)d_in[18];
    const float* cln1_g   = (const float*)d_in[19];
    const float* cln1_b   = (const float*)d_in[20];
    const float* cln2_g   = (const float*)d_in[21];
    const float* cln2_b   = (const float*)d_in[22];
    const float* delta_w  = (const float*)d_in[23];
    const float* delta_b  = (const float*)d_in[24];
    const float* codebook = (const float*)d_in[25];
    const float* dec_w1   = (const float*)d_in[26];
    const float* dec_b1   = (const float*)d_in[27];
    const float* dec_w2   = (const float*)d_in[28];
    const float* dec_b2   = (const float*)d_in[29];
    const float* dec_w3   = (const float*)d_in[30];
    const float* dec_b3   = (const float*)d_in[31];
    float* out = (float*)d_out;
    const long long BSTRIDE = 2048LL*256;

    cudaStream_t s2;
    cudaStreamCreateWithFlags(&s2, cudaStreamNonBlocking);
    cudaEvent_t ev0, evA, evB, evC, evS1, evS2, evD;
    cudaEventCreateWithFlags(&ev0, cudaEventDisableTiming);
    cudaEventCreateWithFlags(&evA, cudaEventDisableTiming);
    cudaEventCreateWithFlags(&evB, cudaEventDisableTiming);
    cudaEventCreateWithFlags(&evC, cudaEventDisableTiming);
    cudaEventCreateWithFlags(&evS1, cudaEventDisableTiming);
    cudaEventCreateWithFlags(&evS2, cudaEventDisableTiming);
    cudaEventCreateWithFlags(&evD, cudaEventDisableTiming);

    // ---- fork: side stream does all input-only work ----
    cudaEventRecord(ev0, 0);
    cudaStreamWaitEvent(s2, ev0, 0);
    GEMMS(s2, dim3(6,1), pos,0,256,0, sa_qkv_w,0,256, nullptr, OFF_QKVP,768,0, 0, 64,768,256, 0,1.f,0);
    cudaEventRecord(evA, s2);
    // scan constants: ws, N1=W2^T, W2^2..W2^8
    wsum_kernel<<<256,256,0,s2>>>(delta_w);
    transpose_w2<<<256,256,0,s2>>>(delta_w);
    GEMMS(s2, dim3(2,2), delta_w+256,0,512,0, nullptr,OFF_N1,256, nullptr, OFF_M2,256,0, 0, 256,256,256, 0,1.f,0);
    GEMMS(s2, dim3(2,2), nullptr,OFF_M2,256,0, nullptr,OFF_N1,256, nullptr, OFF_M3,256,0, 0, 256,256,256, 0,1.f,0);
    GEMMS(s2, dim3(2,2), nullptr,OFF_M3,256,0, nullptr,OFF_N1,256, nullptr, OFF_M4,256,0, 0, 256,256,256, 0,1.f,0);
    GEMMS(s2, dim3(2,2), nullptr,OFF_M4,256,0, nullptr,OFF_N1,256, nullptr, OFF_M5,256,0, 0, 256,256,256, 0,1.f,0);
    GEMMS(s2, dim3(2,2), nullptr,OFF_M5,256,0, nullptr,OFF_N1,256, nullptr, OFF_M6,256,0, 0, 256,256,256, 0,1.f,0);
    GEMMS(s2, dim3(2,2), nullptr,OFF_M6,256,0, nullptr,OFF_N1,256, nullptr, OFF_M7,256,0, 0, 256,256,256, 0,1.f,0);
    GEMMS(s2, dim3(2,2), nullptr,OFF_M7,256,0, nullptr,OFF_N1,256, nullptr, OFF_M8,256,0, 0, 256,256,256, 0,1.f,0);
    cudaEventRecord(evB, s2);
    // VQ codebook norms + decoder LUT chain
    cc_kernel<<<1024,256,0,s2>>>(codebook);
    GEMMS(s2, dim3(8,8), codebook,0,256,0, dec_w1,0,256, dec_b1, OFF_DH1,1024,0, 0, 1024,1024,256, 0,1.f,1);
    GEMMS(s2, dim3(8,8), nullptr,OFF_DH1,1024,0, dec_w2,0,1024, dec_b2, OFF_DH2,1024,0, 0, 1024,1024,1024, 0,1.f,1);
    GEMMS(s2, dim3(1,8), nullptr,OFF_DH2,1024,0, dec_w3,0,1024, dec_b3, OFF_LUT,64,0, 0, 1024,64,1024, 0,1.f,0);
    cudaEventRecord(evC, s2);

    // ---- main pipeline ----
    GEMM(dim3(2,2), obs,0,64,0, patch_w,0,64, patch_b, OFF_BASE,256,0, 0, 256,256,64, 0,1.f,0);
    tok_kernel<<<16384,256>>>(pos);
    GEMM(dim3(6,2), nullptr,OFF_BASE,256,0, sa_qkv_w,0,256, sa_qkv_b, OFF_QKVB,768,0, 0, 256,768,256, 0,1.f,0);
    cudaStreamWaitEvent(0, evA, 0);
    sa_attn<<<1024,256>>>();
    GEMM(dim3(2,128), nullptr,OFF_ATTN,256,0, sa_out_w,0,256, sa_out_b, OFF_BUF,256,0, 0, 16384,256,256, 0,1.f,0);
    ln_kernel<<<16384,256>>>(OFF_BUF,256, OFF_TOK,256, sa_ln_g, sa_ln_b, OFF_TOK,256);
    // ctx layer 0
    GEMM(dim3(6,128), nullptr,OFF_TOK,256,0, cqkv_w,0,256, cqkv_b, OFF_QKV,768,0, 0, 16384,768,256, 0,1.f,0);
    ctx_attn0<<<8192,256>>>(cqkv_b);
    GEMM(dim3(2,512), nullptr,OFF_ATTN,256,0, cout_w,0,256, cout_b, OFF_BUF,256,0, 0, 65536,256,256, 0,1.f,0);
    ln_kernel<<<65536,256>>>(OFF_BUF,256, 0,-2, cln1_g, cln1_b, OFF_XC,256);
    GEMM(dim3(8,512), nullptr,OFF_XC,256,0, cff1_w,0,256, cff1_b, OFF_H,1024,0, 0, 65536,1024,256, 0,1.f,1);
    GEMM(dim3(2,512), nullptr,OFF_H,1024,0, cff2_w,0,1024, cff2_b, OFF_BUF,256,0, 0, 65536,256,1024, 0,1.f,0);
    ln_kernel<<<65536,256>>>(OFF_BUF,256, OFF_XC,256, cln2_g, cln2_b, OFF_XC,256);
    // ctx layer 1
    GEMM(dim3(4,512), nullptr,OFF_XC,256,0, cqkv_w+768*256+256*256,0,256, cqkv_b+768+256, OFF_KV,512,0, 0, 65536,512,256, 0,1.f,0);
    GEMM(dim3(2,128), nullptr,OFF_XC+768,1024,0, cqkv_w+768*256,0,256, cqkv_b+768, OFF_QB1,256,0, 0, 16384,256,256, 0,1.f,0);
    ctx_attn1<<<8192,256>>>();
    GEMM(dim3(2,128), nullptr,OFF_CUR,256,0, cout_w+256*256,0,256, cout_b+256, OFF_BUF,256,0, 0, 16384,256,256, 0,1.f,0);
    ln_kernel<<<16384,256>>>(OFF_BUF,256, OFF_XC+768,1024, cln1_g+256, cln1_b+256, OFF_CUR,256);
    GEMM(dim3(8,128), nullptr,OFF_CUR,256,0, cff1_w+1024*256,0,256, cff1_b+1024, OFF_H,1024,0, 0, 16384,1024,256, 0,1.f,1);
    GEMM(dim3(2,128), nullptr,OFF_H,1024,0, cff2_w+256*1024,0,1024, cff2_b+256, OFF_BUF,256,0, 0, 16384,256,1024, 0,1.f,0);
    ln_kernel<<<16384,256>>>(OFF_CUR,256, OFF_BUF,256, cln2_g+256, cln2_b+256, OFF_CUR,256);
    // ---- delta scan (stride-8) ----
    cudaStreamWaitEvent(0, evB, 0);   // WS + W2 powers ready (also fixes R13's latent WS race)
    GEMM(dim3(2,128), nullptr,OFF_CUR,256,0, nullptr,OFF_WS,256, delta_b, OFF_U,256,0, 0, 16384,256,256, 0,1.f,0);
    copy_s0_both<<<512,256>>>();
    // z values into ct groups (s>=1): depth-0..3 prefix
    GEMM(dim3(2,16,8), nullptr,OFF_U,256,BSTRIDE, delta_w+256,0,512, nullptr, OFF_CT+16384,256,BSTRIDE, OFF_U+16384, 1984,256,256, 2,-1.f,0);
    GEMM(dim3(2,15,8), nullptr,OFF_U,256,BSTRIDE, nullptr,OFF_M2,256, nullptr, OFF_CT+32768,256,BSTRIDE, 0, 1920,256,256, 1, 1.f,0);
    GEMM(dim3(2,15,8), nullptr,OFF_U,256,BSTRIDE, nullptr,OFF_M3,256, nullptr, OFF_CT+49152,256,BSTRIDE, 0, 1856,256,256, 1,-1.f,0);
    // z2 (depth 0..7) written into u-space: grp1 (final ct[1]) and grps 2..7 (parallel, no in-place race)
    GEMM(dim3(2,2,8),  nullptr,OFF_CT,256,BSTRIDE,       nullptr,OFF_M4,256, nullptr, OFF_U+65536,256,BSTRIDE,  OFF_CT+65536,  256,256,256,  2,1.f,0);
    GEMM(dim3(2,12,8), nullptr,OFF_CT+65536,256,BSTRIDE, nullptr,OFF_M4,256, nullptr, OFF_U+131072,256,BSTRIDE, OFF_CT+131072, 1536,256,256, 2,1.f,0);
    copy_grp1<<<2048,256>>>();
    cudaEventRecord(evS1, 0);                       // groups 0,1 final
    cudaStreamWaitEvent(s2, evS1, 0);
    GEMMS(s2, dim3(8,4,8), nullptr,OFF_CT,256,BSTRIDE, codebook,0,256, nullptr, OFF_DOT,1024,2048LL*1024, 0, 512,1024,256, 0,1.f,0);
    // stride-8 sequential steps (3)
    GEMM(dim3(2,4,8), nullptr,OFF_CT,256,BSTRIDE,          nullptr,OFF_M8,256, nullptr, OFF_CT+2*65536,256,BSTRIDE, OFF_U+2*65536, 512,256,256, 2,1.f,0);
    cudaEventRecord(evS2, 0);                       // groups 2,3 final
    cudaStreamWaitEvent(s2, evS2, 0);
    GEMMS(s2, dim3(8,4,8), nullptr,OFF_CT+2*65536,256,BSTRIDE, codebook,0,256, nullptr, OFF_DOT+512*1024,1024,2048LL*1024, 0, 512,1024,256, 0,1.f,0);
    cudaEventRecord(evD, s2);
    GEMM(dim3(2,4,8), nullptr,OFF_CT+2*65536,256,BSTRIDE,  nullptr,OFF_M8,256, nullptr, OFF_CT+4*65536,256,BSTRIDE, OFF_U+4*65536, 512,256,256, 2,1.f,0);
    GEMM(dim3(2,4,8), nullptr,OFF_CT+4*65536,256,BSTRIDE,  nullptr,OFF_M8,256, nullptr, OFF_CT+6*65536,256,BSTRIDE, OFF_U+6*65536, 512,256,256, 2,1.f,0);
    // dot for groups 4..7 on main
    GEMM(dim3(8,8,8), nullptr,OFF_CT+4*65536,256,BSTRIDE, codebook,0,256, nullptr, OFF_DOT+1024*1024,1024,2048LL*1024, 0, 1024,1024,256, 0,1.f,0);
    // ---- VQ select + outputs ----
    cudaStreamWaitEvent(0, evC, 0);
    cudaStreamWaitEvent(0, evD, 0);
    argmin_kernel<<<16384,256>>>();
    recon_kernel<<<4096,256>>>(out);
    idx_kernel<<<64,256>>>(out);
    finalize_kernel<<<1,256>>>(out);

    cudaEventDestroy(ev0); cudaEventDestroy(evA); cudaEventDestroy(evB);
    cudaEventDestroy(evC); cudaEventDestroy(evS1); cudaEventDestroy(evS2);
    cudaEventDestroy(evD);
    cudaStreamDestroy(s2);
}

// round 15
// speedup vs baseline: 1.5079x; 1.5079x over previous
#include <cuda_runtime.h>
#include <math.h>
#include <stdint.h>

// Dims: B=8 S=32 P=64 D=256 H=1024 K=1024 OBS=64 CTX=4 NH=4 dh=64

#define M1 1048576LL
#define OFF_TOK   (0LL)
#define OFF_QKV   (4*M1)
#define OFF_KV    (OFF_QKV)
#define OFF_QB1   (OFF_QKV + 32*M1)
#define OFF_ATTN  (52*M1)
#define OFF_XC    (68*M1)
#define OFF_BUF   (84*M1)
#define OFF_H     (100*M1)
#define OFF_DOT   (OFF_H)
#define OFF_CUR   (164*M1)
#define OFF_U     (168*M1)
#define OFF_CT    (172*M1)
#define OFF_BASE  (176*M1)
#define OFF_WS    (176*M1 + 65536)
#define OFF_CC    (176*M1 + 131072)
#define OFF_QKVB  (176*M1 + 133120)
#define OFF_QKVP  (176*M1 + 329728)
#define OFF_N1    (176*M1 + 378880)
#define OFF_M2    (OFF_N1 + 1*65536)
#define OFF_M3    (OFF_N1 + 2*65536)
#define OFF_M4    (OFF_N1 + 3*65536)
#define OFF_RD    (OFF_N1 + 4*65536)     // per-row best dist (16384)
// decoder scratch in fresh (non-aliased) space so it can run concurrently from t=0
#define OFF_DH1   (186*M1)
#define OFF_DH2   (187*M1)
#define OFF_LUT   (188*M1)

__device__ float g_arena[198000000];   // ~792 MB
__device__ int   g_idx[16384];

// ================= 3xTF32 tensor-core GEMM (round-6 engine, verbatim) =================
__device__ __forceinline__ uint32_t f2tf32(float x) {
    uint32_t r; asm("cvt.rna.tf32.f32 %0, %1;" : "=r"(r) : "f"(x)); return r;
}
__device__ __forceinline__ void mma_tf32(float* c, const uint32_t* a, uint32_t b0, uint32_t b1) {
    asm volatile("mma.sync.aligned.m16n8k8.row.col.f32.tf32.tf32.f32 "
        "{%0,%1,%2,%3}, {%4,%5,%6,%7}, {%8,%9}, {%0,%1,%2,%3};"
        : "+f"(c[0]), "+f"(c[1]), "+f"(c[2]), "+f"(c[3])
        : "r"(a[0]), "r"(a[1]), "r"(a[2]), "r"(a[3]), "r"(b0), "r"(b1));
}
__device__ __forceinline__ void cvt_store8(uint32_t (*H)[136], uint32_t (*L)[136],
                                           int r, float4 v0, float4 v1)
{
    float f[8] = {v0.x,v0.y,v0.z,v0.w,v1.x,v1.y,v1.z,v1.w};
#pragma unroll
    for (int k = 0; k < 8; k++) {
        uint32_t hi = f2tf32(f[k]);
        float lo = f[k] - __uint_as_float(hi);
        H[k][r] = hi;
        L[k][r] = f2tf32(lo);
    }
}

// epi: 0 = bias(+relu), 1 = accumulate into C, 2 = add D
__global__ __launch_bounds__(128) void mma_gemm(
    const float* __restrict__ Aext, long long aOff, int lda, long long aBatch,
    const float* __restrict__ Bext, long long bOff, int ldb,
    const float* __restrict__ biasExt,
    long long cOff, int ldc, long long cBatch,
    long long dOff,
    int M, int N, int K, int epi, float alpha, int relu)
{
    const float* A = (Aext ? Aext : (g_arena + aOff)) + (size_t)blockIdx.z * aBatch;
    const float* B = Bext ? Bext : (g_arena + bOff);
    float* C = g_arena + cOff + (size_t)blockIdx.z * cBatch;
    const float* D = g_arena + dOff + (size_t)blockIdx.z * cBatch;
    __shared__ uint32_t AsH[2][8][136], AsL[2][8][136], BsH[2][8][136], BsL[2][8][136];
    int tid = threadIdx.x, lane = tid & 31, wid = tid >> 5;
    int m0 = blockIdx.y * 128, n0 = blockIdx.x * 128;
    int wm = (wid & 1) * 64, wn = (wid >> 1) * 64;
    const float4 z4 = make_float4(0.f,0.f,0.f,0.f);

    int arow = m0 + tid, brow = n0 + tid;
    const float* Ab = A + (size_t)arow * lda;
    const float* Bb = B + (size_t)brow * ldb;
    bool am = arow < M, bm = brow < N;

    float4 a0,a1,b0,b1;
    a0 = am ? *(const float4*)Ab     : z4;
    a1 = am ? *(const float4*)(Ab+4) : z4;
    b0 = bm ? *(const float4*)Bb     : z4;
    b1 = bm ? *(const float4*)(Bb+4) : z4;
    cvt_store8(AsH[0], AsL[0], tid, a0, a1);
    cvt_store8(BsH[0], BsL[0], tid, b0, b1);
    __syncthreads();

    float acc[4][8][4];
#pragma unroll
    for (int i=0;i<4;i++)
#pragma unroll
        for (int j=0;j<8;j++)
#pragma unroll
            for (int q=0;q<4;q++) acc[i][j][q]=0.f;

    int ak = lane & 3, aq = lane >> 2;
    int nkt = K >> 3;
    for (int kt = 0; kt < nkt; kt++) {
        int buf = kt & 1;
        bool pf = (kt+1) < nkt;
        if (pf) {
            int k0 = (kt+1) << 3;
            a0 = am ? *(const float4*)(Ab+k0)   : z4;
            a1 = am ? *(const float4*)(Ab+k0+4) : z4;
            b0 = bm ? *(const float4*)(Bb+k0)   : z4;
            b1 = bm ? *(const float4*)(Bb+k0+4) : z4;
        }
        uint32_t aH[4][4], aL[4][4];
#pragma unroll
        for (int mi = 0; mi < 4; mi++) {
            int row = wm + mi*16 + aq;
            aH[mi][0]=AsH[buf][ak][row];   aH[mi][1]=AsH[buf][ak][row+8];
            aH[mi][2]=AsH[buf][ak+4][row]; aH[mi][3]=AsH[buf][ak+4][row+8];
            aL[mi][0]=AsL[buf][ak][row];   aL[mi][1]=AsL[buf][ak][row+8];
            aL[mi][2]=AsL[buf][ak+4][row]; aL[mi][3]=AsL[buf][ak+4][row+8];
        }
#pragma unroll
        for (int ni = 0; ni < 8; ni++) {
            int col = wn + ni*8 + aq;
            uint32_t bH0=BsH[buf][ak][col], bH1=BsH[buf][ak+4][col];
            uint32_t bL0=BsL[buf][ak][col], bL1=BsL[buf][ak+4][col];
#pragma unroll
            for (int mi = 0; mi < 4; mi++) {
                mma_tf32(acc[mi][ni], aH[mi], bH0, bH1);
                mma_tf32(acc[mi][ni], aL[mi], bH0, bH1);
                mma_tf32(acc[mi][ni], aH[mi], bL0, bL1);
            }
        }
        if (pf) {
            cvt_store8(AsH[buf^1], AsL[buf^1], tid, a0, a1);
            cvt_store8(BsH[buf^1], BsL[buf^1], tid, b0, b1);
            __syncthreads();
        }
    }
#pragma unroll
    for (int mi = 0; mi < 4; mi++) {
        int r0 = m0 + wm + mi*16 + aq;
#pragma unroll
        for (int ni = 0; ni < 8; ni++) {
            int c0 = n0 + wn + ni*8 + 2*ak;
            if (c0 >= N) continue;
            float v0 = alpha*acc[mi][ni][0], v1 = alpha*acc[mi][ni][1];
            float v2 = alpha*acc[mi][ni][2], v3 = alpha*acc[mi][ni][3];
            if (epi == 0) {
                float bb0 = biasExt ? biasExt[c0]   : 0.f;
                float bb1 = biasExt ? biasExt[c0+1] : 0.f;
                v0+=bb0; v1+=bb1; v2+=bb0; v3+=bb1;
                if (relu) { v0=fmaxf(v0,0.f); v1=fmaxf(v1,0.f); v2=fmaxf(v2,0.f); v3=fmaxf(v3,0.f); }
            } else if (epi == 1) {
                if (r0 < M)   { float2 c = *(float2*)(C + (size_t)r0*ldc + c0);     v0+=c.x; v1+=c.y; }
                if (r0+8 < M) { float2 c = *(float2*)(C + (size_t)(r0+8)*ldc + c0); v2+=c.x; v3+=c.y; }
            } else {
                if (r0 < M)   { float2 d = *(const float2*)(D + (size_t)r0*ldc + c0);     v0+=d.x; v1+=d.y; }
                if (r0+8 < M) { float2 d = *(const float2*)(D + (size_t)(r0+8)*ldc + c0); v2+=d.x; v3+=d.y; }
            }
            if (r0 < M)   *(float2*)(C + (size_t)r0*ldc + c0)     = make_float2(v0,v1);
            if (r0+8 < M) *(float2*)(C + (size_t)(r0+8)*ldc + c0) = make_float2(v2,v3);
        }
    }
}

// ---------------- tok_pre = base[bs] + pos_embed[p] ----------------
__global__ void tok_kernel(const float* __restrict__ pe)
{
    int e = blockIdx.x * 256 + threadIdx.x;
    int d = e & 255, r = e >> 8;
    int bs = r >> 6, p = r & 63;
    g_arena[OFF_TOK + e] = g_arena[OFF_BASE + bs*256 + d] + pe[p*256 + d];
}

// ---------------- self-attention; qkv from qkvb[bs]+qkvp[p] ----------------
__global__ __launch_bounds__(256) void sa_attn()
{
    float* out = g_arena + OFF_ATTN;
    int h  = blockIdx.x & 3;
    int bs = blockIdx.x >> 2;
    __shared__ float Qs[64][65], Ks[64][65], Vs[64][65];
    __shared__ float Ps[8][64];
    int t = threadIdx.x;
    const float* qb = g_arena + OFF_QKVB + bs*768 + h*64;
    const float* qp = g_arena + OFF_QKVP + h*64;
    for (int i = t; i < 4096; i += 256) {
        int rr = i >> 6, cc = i & 63;
        const float* pr = qp + rr*768 + cc;
        Qs[rr][cc] = pr[0]   + qb[cc];
        Ks[rr][cc] = pr[256] + qb[256+cc];
        Vs[rr][cc] = pr[512] + qb[512+cc];
    }
    __syncthreads();
    int w = t >> 5, lane = t & 31;
    for (int qi = w*8; qi < w*8+8; qi++) {
        float s0 = 0.f, s1 = 0.f;
#pragma unroll 8
        for (int d = 0; d < 64; d++) {
            float q = Qs[qi][d];
            s0 = fmaf(q, Ks[lane][d], s0);
            s1 = fmaf(q, Ks[lane+32][d], s1);
        }
        s0 *= 0.125f; s1 *= 0.125f;
        float mx = fmaxf(s0, s1);
#pragma unroll
        for (int o = 16; o; o >>= 1) mx = fmaxf(mx, __shfl_xor_sync(0xffffffffu, mx, o));
        float e0 = expf(s0 - mx), e1 = expf(s1 - mx);
        float sum = e0 + e1;
#pragma unroll
        for (int o = 16; o; o >>= 1) sum += __shfl_xor_sync(0xffffffffu, sum, o);
        float inv = 1.f / sum;
        Ps[w][lane] = e0 * inv; Ps[w][lane+32] = e1 * inv;
        __syncwarp();
        float o0 = 0.f, o1 = 0.f;
#pragma unroll 8
        for (int k = 0; k < 64; k++) {
            float p = Ps[w][k];
            o0 = fmaf(p, Vs[k][lane], o0);
            o1 = fmaf(p, Vs[k][lane+32], o1);
        }
        size_t ob = (size_t)(bs*64 + qi) * 256 + h*64;
        out[ob + lane] = o0;
        out[ob + lane + 32] = o1;
        __syncwarp();
    }
}

// ---------------- LN(x + r); rs==-2: residual = windowed tok gather ----------------
__global__ __launch_bounds__(256) void ln_kernel(long long xOff, int xs,
                                                 long long rOff, int rs,
                                                 const float* __restrict__ g, const float* __restrict__ b,
                                                 long long oOff, int os)
{
    int row = blockIdx.x, t = threadIdx.x;
    int w = t >> 5, lane = t & 31;
    float rres;
    if (rs == -2) {
        int j = row & 3, p = (row >> 2) & 63, s = (row >> 8) & 31, bb = row >> 13;
        int sp = s + j - 3;
        rres = (sp >= 0) ? g_arena[OFF_TOK + ((size_t)((bb*32 + sp)*64 + p))*256 + t] : 0.f;
    } else {
        rres = g_arena[rOff + (size_t)row*rs + t];
    }
    float v = g_arena[xOff + (size_t)row*xs + t] + rres;
    __shared__ float red[8];
    float s = v;
#pragma unroll
    for (int o = 16; o; o >>= 1) s += __shfl_xor_sync(0xffffffffu, s, o);
    if (lane == 0) red[w] = s;
    __syncthreads();
    float mean = (red[0]+red[1]+red[2]+red[3]+red[4]+red[5]+red[6]+red[7]) * (1.f/256.f);
    float dv = v - mean;
    s = dv*dv;
#pragma unroll
    for (int o = 16; o; o >>= 1) s += __shfl_xor_sync(0xffffffffu, s, o);
    __syncthreads();
    if (lane == 0) red[w] = s;
    __syncthreads();
    float var = (red[0]+red[1]+red[2]+red[3]+red[4]+red[5]+red[6]+red[7]) * (1.f/256.f);
    g_arena[oOff + (size_t)row*os + t] = dv * rsqrtf(var + 1e-5f) * g[t] + b[t];
}

// ---------------- ctx layer-0 attention (gather from per-token qkv) ----------------
__global__ __launch_bounds__(256) void ctx_attn0(const float* __restrict__ cqkv_b)
{
    float* out = g_arena + OFF_ATTN;
    const float* qt = g_arena + OFF_QKV;
    int wg = blockIdx.x * 8 + (threadIdx.x >> 5);
    int lane = threadIdx.x & 31;
    int seq = wg >> 2, h = wg & 3;
    int s = (seq >> 6) & 31;
    const float* bq = cqkv_b + h*64 + lane*2;
    float2 q[4], k[4], v[4];
#pragma unroll
    for (int j = 0; j < 4; j++) {
        if (s + j - 3 >= 0) {
            const float* row = qt + (size_t)(seq + (j-3)*64)*768 + h*64 + lane*2;
            q[j] = *(const float2*)row;
            k[j] = *(const float2*)(row + 256);
            v[j] = *(const float2*)(row + 512);
        } else {
            q[j] = *(const float2*)bq;
            k[j] = *(const float2*)(bq + 256);
            v[j] = *(const float2*)(bq + 512);
        }
    }
    float sc[4][4];
#pragma unroll
    for (int j = 0; j < 4; j++)
#pragma unroll
        for (int kk = 0; kk < 4; kk++)
            sc[j][kk] = q[j].x*k[kk].x + q[j].y*k[kk].y;
#pragma unroll
    for (int o = 16; o; o >>= 1)
#pragma unroll
        for (int j = 0; j < 4; j++)
#pragma unroll
            for (int kk = 0; kk < 4; kk++)
                sc[j][kk] += __shfl_xor_sync(0xffffffffu, sc[j][kk], o);
    float p[4][4];
#pragma unroll
    for (int j = 0; j < 4; j++) {
        float mx = -1e30f;
#pragma unroll
        for (int kk = 0; kk < 4; kk++) { sc[j][kk] *= 0.125f; mx = fmaxf(mx, sc[j][kk]); }
        float sum = 0.f;
#pragma unroll
        for (int kk = 0; kk < 4; kk++) { p[j][kk] = expf(sc[j][kk] - mx); sum += p[j][kk]; }
        float inv = 1.f / sum;
#pragma unroll
        for (int kk = 0; kk < 4; kk++) p[j][kk] *= inv;
    }
#pragma unroll
    for (int j = 0; j < 4; j++) {
        float2 o2 = make_float2(0.f, 0.f);
#pragma unroll
        for (int kk = 0; kk < 4; kk++) { o2.x = fmaf(p[j][kk], v[kk].x, o2.x); o2.y = fmaf(p[j][kk], v[kk].y, o2.y); }
        *(float2*)(out + ((size_t)seq*4 + j)*256 + h*64 + lane*2) = o2;
    }
}

// ---------------- ctx layer-1 attention (Q at j=3 only) ----------------
__global__ __launch_bounds__(256) void ctx_attn1()
{
    int wg = blockIdx.x * 8 + (threadIdx.x >> 5);
    int lane = threadIdx.x & 31;
    int seq = wg >> 2, h = wg & 3;
    float2 q = *(const float2*)(g_arena + OFF_QB1 + (size_t)seq*256 + h*64 + lane*2);
    float2 k[4], v[4];
#pragma unroll
    for (int j = 0; j < 4; j++) {
        const float* r = g_arena + OFF_KV + (size_t)(seq*4 + j)*512 + h*64 + lane*2;
        k[j] = *(const float2*)r;
        v[j] = *(const float2*)(r + 256);
    }
    float sc[4];
#pragma unroll
    for (int kk = 0; kk < 4; kk++) sc[kk] = q.x*k[kk].x + q.y*k[kk].y;
#pragma unroll
    for (int o = 16; o; o >>= 1)
#pragma unroll
        for (int kk = 0; kk < 4; kk++)
            sc[kk] += __shfl_xor_sync(0xffffffffu, sc[kk], o);
    float mx = -1e30f;
#pragma unroll
    for (int kk = 0; kk < 4; kk++) { sc[kk] *= 0.125f; mx = fmaxf(mx, sc[kk]); }
    float sum = 0.f; float p[4];
#pragma unroll
    for (int kk = 0; kk < 4; kk++) { p[kk] = expf(sc[kk] - mx); sum += p[kk]; }
    float inv = 1.f / sum;
    float2 o2 = make_float2(0.f, 0.f);
#pragma unroll
    for (int kk = 0; kk < 4; kk++) { o2.x = fmaf(p[kk]*inv, v[kk].x, o2.x); o2.y = fmaf(p[kk]*inv, v[kk].y, o2.y); }
    *(float2*)(g_arena + OFF_CUR + (size_t)seq*256 + h*64 + lane*2) = o2;
}

// ---------------- delta helpers ----------------
__global__ void wsum_kernel(const float* __restrict__ dw)
{
    int e = blockIdx.x * 256 + threadIdx.x;
    int d = e >> 8, k = e & 255;
    g_arena[OFF_WS + e] = dw[d*512 + k] + dw[d*512 + 256 + k];
}
// write cur[b][0] rows into BOTH u[b][0] and ct[b][0]
__global__ void copy_s0_both()
{
    int e = blockIdx.x * 256 + threadIdx.x;   // 131072
    int d = e & 255, p = (e >> 8) & 63, b = e >> 14;
    size_t off = ((size_t)(b*2048 + p))*256 + d;
    float v = g_arena[OFF_CUR + off];
    g_arena[OFF_U  + off] = v;
    g_arena[OFF_CT + off] = v;
}
__global__ void transpose_w2(const float* __restrict__ dw)
{
    int n = blockIdx.x, k = threadIdx.x;
    g_arena[OFF_N1 + (size_t)n*256 + k] = dw[(size_t)k*512 + 256 + n];
}

// ---------------- VQ ----------------
__global__ void cc_kernel(const float* __restrict__ cb)
{
    int row = blockIdx.x, t = threadIdx.x;
    float v = cb[row*256 + t];
    __shared__ float red[256];
    red[t] = v*v; __syncthreads();
    for (int o = 128; o; o >>= 1) { if (t < o) red[t] += red[t+o]; __syncthreads(); }
    if (t == 0) g_arena[OFF_CC + row] = red[0];
}
__global__ __launch_bounds__(256) void argmin_kernel()
{
    int row = blockIdx.x, t = threadIdx.x;
    float x = g_arena[OFF_CT + (size_t)row*256 + t];
    __shared__ float red[256];
    red[t] = x*x; __syncthreads();
    for (int o = 128; o; o >>= 1) { if (t < o) red[t] += red[t+o]; __syncthreads(); }
    float xx = red[0];
    __syncthreads();
    const float* dot = g_arena + OFF_DOT + (size_t)row*1024;
    float best = 3.4e38f; int bi = 0;
    for (int j = t; j < 1024; j += 256) {
        float dist = xx - 2.f*dot[j] + g_arena[OFF_CC + j];
        if (dist < best) { best = dist; bi = j; }
    }
    __shared__ float rv[256];
    __shared__ int   ri[256];
    rv[t] = best; ri[t] = bi; __syncthreads();
    for (int o = 128; o; o >>= 1) {
        if (t < o) {
            float v2 = rv[t+o]; int i2 = ri[t+o];
            if (v2 < rv[t] || (v2 == rv[t] && i2 < ri[t])) { rv[t] = v2; ri[t] = i2; }
        }
        __syncthreads();
    }
    if (t == 0) {
        g_idx[row] = ri[0];
        g_arena[OFF_RD + row] = rv[0];   // = sum((ct-q)^2) for this row
    }
}

// ---------------- output writers ----------------
__global__ void recon_kernel(float* __restrict__ out)
{
    int e = blockIdx.x * 256 + threadIdx.x;
    out[e] = g_arena[OFF_LUT + g_idx[e >> 6]*64 + (e & 63)];
}
__global__ void idx_kernel(float* __restrict__ out)
{
    int r = blockIdx.x * 256 + threadIdx.x;
    out[1048576 + r] = (float)g_idx[r];
}
// losses from per-row best dists (deterministic fixed-order sum)
__global__ void finalize_kernel(float* __restrict__ out)
{
    int t = threadIdx.x;
    float acc = 0.f;
    for (int k = 0; k < 64; k++)
        acc += g_arena[OFF_RD + t + 256*k];
    __shared__ float red[256];
    red[t] = acc; __syncthreads();
    for (int o = 128; o; o >>= 1) { if (t < o) red[t] += red[t+o]; __syncthreads(); }
    if (t == 0) {
        float mse = red[0] / 4194304.f;
        out[1064960] = 0.25f * mse;
        out[1064961] = mse;
        out[1064962] = 1.25f * mse;
    }
}

#define GEMM(grid, Aext,aOff,lda,aB, Bext,bOff,ldb, bias, cOff,ldc,cB, dOff, M,N,K, epi,alpha,relu) \
    mma_gemm<<<grid,128>>>(Aext,aOff,lda,aB, Bext,bOff,ldb, bias, cOff,ldc,cB, dOff, M,N,K, epi,alpha,relu)
#define GEMMS(st, grid, Aext,aOff,lda,aB, Bext,bOff,ldb, bias, cOff,ldc,cB, dOff, M,N,K, epi,alpha,relu) \
    mma_gemm<<<grid,128,0,st>>>(Aext,aOff,lda,aB, Bext,bOff,ldb, bias, cOff,ldc,cB, dOff, M,N,K, epi,alpha,relu)

// ---------------- orchestration: R13 schedule + argmin-byproduct losses ----------------
extern "C" void kernel_launch(void* const* d_in, const int* in_sizes, int n_in,
                              void* d_out, int out_size)
{
    const float* obs      = (const float*)d_in[0];
    const float* patch_w  = (const float*)d_in[2];
    const float* patch_b  = (const float*)d_in[3];
    const float* pos      = (const float*)d_in[4];
    const float* sa_qkv_w = (const float*)d_in[5];
    const float* sa_qkv_b = (const float*)d_in[6];
    const float* sa_out_w = (const float*)d_in[7];
    const float* sa_out_b = (const float*)d_in[8];
    const float* sa_ln_g  = (const float*)d_in[9];
    const float* sa_ln_b  = (const float*)d_in[10];
    const float* cqkv_w   = (const float*)d_in[11];
    const float* cqkv_b   = (const float*)d_in[12];
    const float* cout_w   = (const float*)d_in[13];
    const float* cout_b   = (const float*)d_in[14];
    const float* cff1_w   = (const float*)d_in[15];
    const float* cff1_b   = (const float*)d_in[16];
    const float* cff2_w   = (const float*)d_in[17];
    const float* cff2_b   = (const float*)d_in[18];
    const float* cln1_g   = (const float*)d_in[19];
    const float* cln1_b   = (const float*)d_in[20];
    const float* cln2_g   = (const float*)d_in[21];
    const float* cln2_b   = (const float*)d_in[22];
    const float* delta_w  = (const float*)d_in[23];
    const float* delta_b  = (const float*)d_in[24];
    const float* codebook = (const float*)d_in[25];
    const float* dec_w1   = (const float*)d_in[26];
    const float* dec_b1   = (const float*)d_in[27];
    const float* dec_w2   = (const float*)d_in[28];
    const float* dec_b2   = (const float*)d_in[29];
    const float* dec_w3   = (const float*)d_in[30];
    const float* dec_b3   = (const float*)d_in[31];
    float* out = (float*)d_out;
    const long long BSTRIDE = 2048LL*256;

    // side stream + events (coarse fork/join only — R13 pattern)
    cudaStream_t s2;
    cudaStreamCreateWithFlags(&s2, cudaStreamNonBlocking);
    cudaEvent_t ev0, evA, evB, evC;
    cudaEventCreateWithFlags(&ev0, cudaEventDisableTiming);
    cudaEventCreateWithFlags(&evA, cudaEventDisableTiming);
    cudaEventCreateWithFlags(&evB, cudaEventDisableTiming);
    cudaEventCreateWithFlags(&evC, cudaEventDisableTiming);

    // ---- fork: side stream does ALL input-only work concurrently with main pipeline ----
    cudaEventRecord(ev0, 0);
    cudaStreamWaitEvent(s2, ev0, 0);
    //   qkvp = pos @ sa_qkv_w^T           (needed by sa_attn)
    GEMMS(s2, dim3(6,1), pos,0,256,0, sa_qkv_w,0,256, nullptr, OFF_QKVP,768,0, 0, 64,768,256, 0,1.f,0);
    cudaEventRecord(evA, s2);
    //   delta-scan constants: ws, N1=W2^T, M2=W2^2, M3=W2^3, M4=W2^4   (needed by scan)
    wsum_kernel<<<256,256,0,s2>>>(delta_w);
    transpose_w2<<<256,256,0,s2>>>(delta_w);
    GEMMS(s2, dim3(2,2), delta_w+256,0,512,0, nullptr,OFF_N1,256, nullptr, OFF_M2,256,0, 0, 256,256,256, 0,1.f,0);
    GEMMS(s2, dim3(2,2), nullptr,OFF_M2,256,0, nullptr,OFF_N1,256, nullptr, OFF_M3,256,0, 0, 256,256,256, 0,1.f,0);
    GEMMS(s2, dim3(2,2), nullptr,OFF_M3,256,0, nullptr,OFF_N1,256, nullptr, OFF_M4,256,0, 0, 256,256,256, 0,1.f,0);
    cudaEventRecord(evB, s2);
    //   VQ codebook norms + decoder LUT chain   (needed by argmin / recon)
    cc_kernel<<<1024,256,0,s2>>>(codebook);
    GEMMS(s2, dim3(8,8), codebook,0,256,0, dec_w1,0,256, dec_b1, OFF_DH1,1024,0, 0, 1024,1024,256, 0,1.f,1);
    GEMMS(s2, dim3(8,8), nullptr,OFF_DH1,1024,0, dec_w2,0,1024, dec_b2, OFF_DH2,1024,0, 0, 1024,1024,1024, 0,1.f,1);
    GEMMS(s2, dim3(1,8), nullptr,OFF_DH2,1024,0, dec_w3,0,1024, dec_b3, OFF_LUT,64,0, 0, 1024,64,1024, 0,1.f,0);
    cudaEventRecord(evC, s2);

    // ---- main pipeline ----
    // 1. patch projection
    GEMM(dim3(2,2), obs,0,64,0, patch_w,0,64, patch_b, OFF_BASE,256,0, 0, 256,256,64, 0,1.f,0);
    tok_kernel<<<16384,256>>>(pos);
    // 2. sa QKV decomposition + attention + out-proj + LN
    GEMM(dim3(6,2), nullptr,OFF_BASE,256,0, sa_qkv_w,0,256, sa_qkv_b, OFF_QKVB,768,0, 0, 256,768,256, 0,1.f,0);
    cudaStreamWaitEvent(0, evA, 0);
    sa_attn<<<1024,256>>>();
    GEMM(dim3(2,128), nullptr,OFF_ATTN,256,0, sa_out_w,0,256, sa_out_b, OFF_BUF,256,0, 0, 16384,256,256, 0,1.f,0);
    ln_kernel<<<16384,256>>>(OFF_BUF,256, OFF_TOK,256, sa_ln_g, sa_ln_b, OFF_TOK,256);
    // 3. ctx layer 0 (window residual gathered in LN)
    GEMM(dim3(6,128), nullptr,OFF_TOK,256,0, cqkv_w,0,256, cqkv_b, OFF_QKV,768,0, 0, 16384,768,256, 0,1.f,0);
    ctx_attn0<<<8192,256>>>(cqkv_b);
    GEMM(dim3(2,512), nullptr,OFF_ATTN,256,0, cout_w,0,256, cout_b, OFF_BUF,256,0, 0, 65536,256,256, 0,1.f,0);
    ln_kernel<<<65536,256>>>(OFF_BUF,256, 0,-2, cln1_g, cln1_b, OFF_XC,256);
    GEMM(dim3(8,512), nullptr,OFF_XC,256,0, cff1_w,0,256, cff1_b, OFF_H,1024,0, 0, 65536,1024,256, 0,1.f,1);
    GEMM(dim3(2,512), nullptr,OFF_H,1024,0, cff2_w,0,1024, cff2_b, OFF_BUF,256,0, 0, 65536,256,1024, 0,1.f,0);
    ln_kernel<<<65536,256>>>(OFF_BUF,256, OFF_XC,256, cln2_g, cln2_b, OFF_XC,256);
    // 4. ctx layer 1 (Q only at j=3)
    GEMM(dim3(4,512), nullptr,OFF_XC,256,0, cqkv_w+768*256+256*256,0,256, cqkv_b+768+256, OFF_KV,512,0, 0, 65536,512,256, 0,1.f,0);
    GEMM(dim3(2,128), nullptr,OFF_XC+768,1024,0, cqkv_w+768*256,0,256, cqkv_b+768, OFF_QB1,256,0, 0, 16384,256,256, 0,1.f,0);
    ctx_attn1<<<8192,256>>>();
    GEMM(dim3(2,128), nullptr,OFF_CUR,256,0, cout_w+256*256,0,256, cout_b+256, OFF_BUF,256,0, 0, 16384,256,256, 0,1.f,0);
    ln_kernel<<<16384,256>>>(OFF_BUF,256, OFF_XC+768,1024, cln1_g+256, cln1_b+256, OFF_CUR,256);
    GEMM(dim3(8,128), nullptr,OFF_CUR,256,0, cff1_w+1024*256,0,256, cff1_b+1024, OFF_H,1024,0, 0, 16384,1024,256, 0,1.f,1);
    GEMM(dim3(2,128), nullptr,OFF_H,1024,0, cff2_w+256*1024,0,1024, cff2_b+256, OFF_BUF,256,0, 0, 16384,256,1024, 0,1.f,0);
    ln_kernel<<<16384,256>>>(OFF_CUR,256, OFF_BUF,256, cln2_g+256, cln2_b+256, OFF_CUR,256);
    // 5. delta scan (stride-4; constants from side stream; join BEFORE WS use)
    cudaStreamWaitEvent(0, evB, 0);
    GEMM(dim3(2,128), nullptr,OFF_CUR,256,0, nullptr,OFF_WS,256, delta_b, OFF_U,256,0, 0, 16384,256,256, 0,1.f,0);
    copy_s0_both<<<512,256>>>();
    GEMM(dim3(2,16,8), nullptr,OFF_U,256,BSTRIDE, delta_w+256,0,512, nullptr, OFF_CT+16384,256,BSTRIDE, OFF_U+16384, 1984,256,256, 2,-1.f,0);
    GEMM(dim3(2,15,8), nullptr,OFF_U,256,BSTRIDE, nullptr,OFF_M2,256, nullptr, OFF_CT+32768,256,BSTRIDE, 0, 1920,256,256, 1, 1.f,0);
    GEMM(dim3(2,15,8), nullptr,OFF_U,256,BSTRIDE, nullptr,OFF_M3,256, nullptr, OFF_CT+49152,256,BSTRIDE, 0, 1856,256,256, 1,-1.f,0);
    for (int g = 1; g <= 7; g++)
        GEMM(dim3(2,2,8), nullptr,OFF_CT+(g-1)*65536LL,256,BSTRIDE, nullptr,OFF_M4,256, nullptr, OFF_CT+g*65536LL,256,BSTRIDE, 0, 256,256,256, 1,1.f,0);
    // 6. VQ (cc + decoder LUT come from side stream)
    GEMM(dim3(8,128), nullptr,OFF_CT,256,0, codebook,0,256, nullptr, OFF_DOT,1024,0, 0, 16384,1024,256, 0,1.f,0);
    cudaStreamWaitEvent(0, evC, 0);
    argmin_kernel<<<16384,256>>>();
    // 7. outputs (losses from argmin byproduct — vq_sumsq eliminated)
    recon_kernel<<<4096,256>>>(out);
    idx_kernel<<<64,256>>>(out);
    finalize_kernel<<<1,256>>>(out);

    cudaEventDestroy(ev0);
    cudaEventDestroy(evA);
    cudaEventDestroy(evB);
    cudaEventDestroy(evC);
    cudaStreamDestroy(s2);
}

// round 17
// speedup vs baseline: 1.5345x; 1.0176x over previous
#include <cuda_runtime.h>
#include <math.h>
#include <stdint.h>

// Dims: B=8 S=32 P=64 D=256 H=1024 K=1024 OBS=64 CTX=4 NH=4 dh=64

#define M1 1048576LL
#define OFF_TOK   (0LL)
#define OFF_QKV   (4*M1)
#define OFF_KV    (OFF_QKV)
#define OFF_QB1   (OFF_QKV + 32*M1)
#define OFF_ATTN  (52*M1)
#define OFF_XC    (68*M1)
#define OFF_BUF   (84*M1)
#define OFF_H     (100*M1)
#define OFF_DOT   (OFF_H)
#define OFF_CUR   (164*M1)
#define OFF_U     (168*M1)
#define OFF_CT    (172*M1)
#define OFF_BASE  (176*M1)
#define OFF_WS    (176*M1 + 65536)
#define OFF_CC    (176*M1 + 131072)
#define OFF_QKVB  (176*M1 + 133120)
#define OFF_QKVP  (176*M1 + 329728)
#define OFF_N1    (176*M1 + 378880)
#define OFF_M2    (OFF_N1 + 1*65536)
#define OFF_M3    (OFF_N1 + 2*65536)
#define OFF_M4    (OFF_N1 + 3*65536)
#define OFF_M5    (OFF_N1 + 4*65536)
#define OFF_M6    (OFF_N1 + 5*65536)
#define OFF_M7    (OFF_N1 + 6*65536)
#define OFF_M8    (OFF_N1 + 7*65536)
#define OFF_RD    (OFF_N1 + 8*65536)     // per-row best dist (16384)
// decoder scratch in fresh (non-aliased) space so it can run concurrently from t=0
#define OFF_DH1   (186*M1)
#define OFF_DH2   (187*M1)
#define OFF_LUT   (188*M1)

__device__ float g_arena[198000000];   // ~792 MB
__device__ int   g_idx[16384];

// ================= 3xTF32 tensor-core GEMM (round-6 engine, verbatim) =================
__device__ __forceinline__ uint32_t f2tf32(float x) {
    uint32_t r; asm("cvt.rna.tf32.f32 %0, %1;" : "=r"(r) : "f"(x)); return r;
}
__device__ __forceinline__ void mma_tf32(float* c, const uint32_t* a, uint32_t b0, uint32_t b1) {
    asm volatile("mma.sync.aligned.m16n8k8.row.col.f32.tf32.tf32.f32 "
        "{%0,%1,%2,%3}, {%4,%5,%6,%7}, {%8,%9}, {%0,%1,%2,%3};"
        : "+f"(c[0]), "+f"(c[1]), "+f"(c[2]), "+f"(c[3])
        : "r"(a[0]), "r"(a[1]), "r"(a[2]), "r"(a[3]), "r"(b0), "r"(b1));
}
__device__ __forceinline__ void cvt_store8(uint32_t (*H)[136], uint32_t (*L)[136],
                                           int r, float4 v0, float4 v1)
{
    float f[8] = {v0.x,v0.y,v0.z,v0.w,v1.x,v1.y,v1.z,v1.w};
#pragma unroll
    for (int k = 0; k < 8; k++) {
        uint32_t hi = f2tf32(f[k]);
        float lo = f[k] - __uint_as_float(hi);
        H[k][r] = hi;
        L[k][r] = f2tf32(lo);
    }
}

// epi: 0 = bias(+relu), 1 = accumulate into C, 2 = add D
__global__ __launch_bounds__(128) void mma_gemm(
    const float* __restrict__ Aext, long long aOff, int lda, long long aBatch,
    const float* __restrict__ Bext, long long bOff, int ldb,
    const float* __restrict__ biasExt,
    long long cOff, int ldc, long long cBatch,
    long long dOff,
    int M, int N, int K, int epi, float alpha, int relu)
{
    const float* A = (Aext ? Aext : (g_arena + aOff)) + (size_t)blockIdx.z * aBatch;
    const float* B = Bext ? Bext : (g_arena + bOff);
    float* C = g_arena + cOff + (size_t)blockIdx.z * cBatch;
    const float* D = g_arena + dOff + (size_t)blockIdx.z * cBatch;
    __shared__ uint32_t AsH[2][8][136], AsL[2][8][136], BsH[2][8][136], BsL[2][8][136];
    int tid = threadIdx.x, lane = tid & 31, wid = tid >> 5;
    int m0 = blockIdx.y * 128, n0 = blockIdx.x * 128;
    int wm = (wid & 1) * 64, wn = (wid >> 1) * 64;
    const float4 z4 = make_float4(0.f,0.f,0.f,0.f);

    int arow = m0 + tid, brow = n0 + tid;
    const float* Ab = A + (size_t)arow * lda;
    const float* Bb = B + (size_t)brow * ldb;
    bool am = arow < M, bm = brow < N;

    float4 a0,a1,b0,b1;
    a0 = am ? *(const float4*)Ab     : z4;
    a1 = am ? *(const float4*)(Ab+4) : z4;
    b0 = bm ? *(const float4*)Bb     : z4;
    b1 = bm ? *(const float4*)(Bb+4) : z4;
    cvt_store8(AsH[0], AsL[0], tid, a0, a1);
    cvt_store8(BsH[0], BsL[0], tid, b0, b1);
    __syncthreads();

    float acc[4][8][4];
#pragma unroll
    for (int i=0;i<4;i++)
#pragma unroll
        for (int j=0;j<8;j++)
#pragma unroll
            for (int q=0;q<4;q++) acc[i][j][q]=0.f;

    int ak = lane & 3, aq = lane >> 2;
    int nkt = K >> 3;
    for (int kt = 0; kt < nkt; kt++) {
        int buf = kt & 1;
        bool pf = (kt+1) < nkt;
        if (pf) {
            int k0 = (kt+1) << 3;
            a0 = am ? *(const float4*)(Ab+k0)   : z4;
            a1 = am ? *(const float4*)(Ab+k0+4) : z4;
            b0 = bm ? *(const float4*)(Bb+k0)   : z4;
            b1 = bm ? *(const float4*)(Bb+k0+4) : z4;
        }
        uint32_t aH[4][4], aL[4][4];
#pragma unroll
        for (int mi = 0; mi < 4; mi++) {
            int row = wm + mi*16 + aq;
            aH[mi][0]=AsH[buf][ak][row];   aH[mi][1]=AsH[buf][ak][row+8];
            aH[mi][2]=AsH[buf][ak+4][row]; aH[mi][3]=AsH[buf][ak+4][row+8];
            aL[mi][0]=AsL[buf][ak][row];   aL[mi][1]=AsL[buf][ak][row+8];
            aL[mi][2]=AsL[buf][ak+4][row]; aL[mi][3]=AsL[buf][ak+4][row+8];
        }
#pragma unroll
        for (int ni = 0; ni < 8; ni++) {
            int col = wn + ni*8 + aq;
            uint32_t bH0=BsH[buf][ak][col], bH1=BsH[buf][ak+4][col];
            uint32_t bL0=BsL[buf][ak][col], bL1=BsL[buf][ak+4][col];
#pragma unroll
            for (int mi = 0; mi < 4; mi++) {
                mma_tf32(acc[mi][ni], aH[mi], bH0, bH1);
                mma_tf32(acc[mi][ni], aL[mi], bH0, bH1);
                mma_tf32(acc[mi][ni], aH[mi], bL0, bL1);
            }
        }
        if (pf) {
            cvt_store8(AsH[buf^1], AsL[buf^1], tid, a0, a1);
            cvt_store8(BsH[buf^1], BsL[buf^1], tid, b0, b1);
            __syncthreads();
        }
    }
#pragma unroll
    for (int mi = 0; mi < 4; mi++) {
        int r0 = m0 + wm + mi*16 + aq;
#pragma unroll
        for (int ni = 0; ni < 8; ni++) {
            int c0 = n0 + wn + ni*8 + 2*ak;
            if (c0 >= N) continue;
            float v0 = alpha*acc[mi][ni][0], v1 = alpha*acc[mi][ni][1];
            float v2 = alpha*acc[mi][ni][2], v3 = alpha*acc[mi][ni][3];
            if (epi == 0) {
                float bb0 = biasExt ? biasExt[c0]   : 0.f;
                float bb1 = biasExt ? biasExt[c0+1] : 0.f;
                v0+=bb0; v1+=bb1; v2+=bb0; v3+=bb1;
                if (relu) { v0=fmaxf(v0,0.f); v1=fmaxf(v1,0.f); v2=fmaxf(v2,0.f); v3=fmaxf(v3,0.f); }
            } else if (epi == 1) {
                if (r0 < M)   { float2 c = *(float2*)(C + (size_t)r0*ldc + c0);     v0+=c.x; v1+=c.y; }
                if (r0+8 < M) { float2 c = *(float2*)(C + (size_t)(r0+8)*ldc + c0); v2+=c.x; v3+=c.y; }
            } else {
                if (r0 < M)   { float2 d = *(const float2*)(D + (size_t)r0*ldc + c0);     v0+=d.x; v1+=d.y; }
                if (r0+8 < M) { float2 d = *(const float2*)(D + (size_t)(r0+8)*ldc + c0); v2+=d.x; v3+=d.y; }
            }
            if (r0 < M)   *(float2*)(C + (size_t)r0*ldc + c0)     = make_float2(v0,v1);
            if (r0+8 < M) *(float2*)(C + (size_t)(r0+8)*ldc + c0) = make_float2(v2,v3);
        }
    }
}

// ---------------- tok_pre = base[bs] + pos_embed[p] ----------------
__global__ void tok_kernel(const float* __restrict__ pe)
{
    int e = blockIdx.x * 256 + threadIdx.x;
    int d = e & 255, r = e >> 8;
    int bs = r >> 6, p = r & 63;
    g_arena[OFF_TOK + e] = g_arena[OFF_BASE + bs*256 + d] + pe[p*256 + d];
}

// ---------------- self-attention; qkv from qkvb[bs]+qkvp[p] ----------------
__global__ __launch_bounds__(256) void sa_attn()
{
    float* out = g_arena + OFF_ATTN;
    int h  = blockIdx.x & 3;
    int bs = blockIdx.x >> 2;
    __shared__ float Qs[64][65], Ks[64][65], Vs[64][65];
    __shared__ float Ps[8][64];
    int t = threadIdx.x;
    const float* qb = g_arena + OFF_QKVB + bs*768 + h*64;
    const float* qp = g_arena + OFF_QKVP + h*64;
    for (int i = t; i < 4096; i += 256) {
        int rr = i >> 6, cc = i & 63;
        const float* pr = qp + rr*768 + cc;
        Qs[rr][cc] = pr[0]   + qb[cc];
        Ks[rr][cc] = pr[256] + qb[256+cc];
        Vs[rr][cc] = pr[512] + qb[512+cc];
    }
    __syncthreads();
    int w = t >> 5, lane = t & 31;
    for (int qi = w*8; qi < w*8+8; qi++) {
        float s0 = 0.f, s1 = 0.f;
#pragma unroll 8
        for (int d = 0; d < 64; d++) {
            float q = Qs[qi][d];
            s0 = fmaf(q, Ks[lane][d], s0);
            s1 = fmaf(q, Ks[lane+32][d], s1);
        }
        s0 *= 0.125f; s1 *= 0.125f;
        float mx = fmaxf(s0, s1);
#pragma unroll
        for (int o = 16; o; o >>= 1) mx = fmaxf(mx, __shfl_xor_sync(0xffffffffu, mx, o));
        float e0 = expf(s0 - mx), e1 = expf(s1 - mx);
        float sum = e0 + e1;
#pragma unroll
        for (int o = 16; o; o >>= 1) sum += __shfl_xor_sync(0xffffffffu, sum, o);
        float inv = 1.f / sum;
        Ps[w][lane] = e0 * inv; Ps[w][lane+32] = e1 * inv;
        __syncwarp();
        float o0 = 0.f, o1 = 0.f;
#pragma unroll 8
        for (int k = 0; k < 64; k++) {
            float p = Ps[w][k];
            o0 = fmaf(p, Vs[k][lane], o0);
            o1 = fmaf(p, Vs[k][lane+32], o1);
        }
        size_t ob = (size_t)(bs*64 + qi) * 256 + h*64;
        out[ob + lane] = o0;
        out[ob + lane + 32] = o1;
        __syncwarp();
    }
}

// ---------------- LN(x + r); rs==-2: residual = windowed tok gather ----------------
__global__ __launch_bounds__(256) void ln_kernel(long long xOff, int xs,
                                                 long long rOff, int rs,
                                                 const float* __restrict__ g, const float* __restrict__ b,
                                                 long long oOff, int os)
{
    int row = blockIdx.x, t = threadIdx.x;
    int w = t >> 5, lane = t & 31;
    float rres;
    if (rs == -2) {
        int j = row & 3, p = (row >> 2) & 63, s = (row >> 8) & 31, bb = row >> 13;
        int sp = s + j - 3;
        rres = (sp >= 0) ? g_arena[OFF_TOK + ((size_t)((bb*32 + sp)*64 + p))*256 + t] : 0.f;
    } else {
        rres = g_arena[rOff + (size_t)row*rs + t];
    }
    float v = g_arena[xOff + (size_t)row*xs + t] + rres;
    __shared__ float red[8];
    float s = v;
#pragma unroll
    for (int o = 16; o; o >>= 1) s += __shfl_xor_sync(0xffffffffu, s, o);
    if (lane == 0) red[w] = s;
    __syncthreads();
    float mean = (red[0]+red[1]+red[2]+red[3]+red[4]+red[5]+red[6]+red[7]) * (1.f/256.f);
    float dv = v - mean;
    s = dv*dv;
#pragma unroll
    for (int o = 16; o; o >>= 1) s += __shfl_xor_sync(0xffffffffu, s, o);
    __syncthreads();
    if (lane == 0) red[w] = s;
    __syncthreads();
    float var = (red[0]+red[1]+red[2]+red[3]+red[4]+red[5]+red[6]+red[7]) * (1.f/256.f);
    g_arena[oOff + (size_t)row*os + t] = dv * rsqrtf(var + 1e-5f) * g[t] + b[t];
}

// ---------------- ctx layer-0 attention (gather from per-token qkv) ----------------
__global__ __launch_bounds__(256) void ctx_attn0(const float* __restrict__ cqkv_b)
{
    float* out = g_arena + OFF_ATTN;
    const float* qt = g_arena + OFF_QKV;
    int wg = blockIdx.x * 8 + (threadIdx.x >> 5);
    int lane = threadIdx.x & 31;
    int seq = wg >> 2, h = wg & 3;
    int s = (seq >> 6) & 31;
    const float* bq = cqkv_b + h*64 + lane*2;
    float2 q[4], k[4], v[4];
#pragma unroll
    for (int j = 0; j < 4; j++) {
        if (s + j - 3 >= 0) {
            const float* row = qt + (size_t)(seq + (j-3)*64)*768 + h*64 + lane*2;
            q[j] = *(const float2*)row;
            k[j] = *(const float2*)(row + 256);
            v[j] = *(const float2*)(row + 512);
        } else {
            q[j] = *(const float2*)bq;
            k[j] = *(const float2*)(bq + 256);
            v[j] = *(const float2*)(bq + 512);
        }
    }
    float sc[4][4];
#pragma unroll
    for (int j = 0; j < 4; j++)
#pragma unroll
        for (int kk = 0; kk < 4; kk++)
            sc[j][kk] = q[j].x*k[kk].x + q[j].y*k[kk].y;
#pragma unroll
    for (int o = 16; o; o >>= 1)
#pragma unroll
        for (int j = 0; j < 4; j++)
#pragma unroll
            for (int kk = 0; kk < 4; kk++)
                sc[j][kk] += __shfl_xor_sync(0xffffffffu, sc[j][kk], o);
    float p[4][4];
#pragma unroll
    for (int j = 0; j < 4; j++) {
        float mx = -1e30f;
#pragma unroll
        for (int kk = 0; kk < 4; kk++) { sc[j][kk] *= 0.125f; mx = fmaxf(mx, sc[j][kk]); }
        float sum = 0.f;
#pragma unroll
        for (int kk = 0; kk < 4; kk++) { p[j][kk] = expf(sc[j][kk] - mx); sum += p[j][kk]; }
        float inv = 1.f / sum;
#pragma unroll
        for (int kk = 0; kk < 4; kk++) p[j][kk] *= inv;
    }
#pragma unroll
    for (int j = 0; j < 4; j++) {
        float2 o2 = make_float2(0.f, 0.f);
#pragma unroll
        for (int kk = 0; kk < 4; kk++) { o2.x = fmaf(p[j][kk], v[kk].x, o2.x); o2.y = fmaf(p[j][kk], v[kk].y, o2.y); }
        *(float2*)(out + ((size_t)seq*4 + j)*256 + h*64 + lane*2) = o2;
    }
}

// ---------------- ctx layer-1 attention (Q at j=3 only) ----------------
__global__ __launch_bounds__(256) void ctx_attn1()
{
    int wg = blockIdx.x * 8 + (threadIdx.x >> 5);
    int lane = threadIdx.x & 31;
    int seq = wg >> 2, h = wg & 3;
    float2 q = *(const float2*)(g_arena + OFF_QB1 + (size_t)seq*256 + h*64 + lane*2);
    float2 k[4], v[4];
#pragma unroll
    for (int j = 0; j < 4; j++) {
        const float* r = g_arena + OFF_KV + (size_t)(seq*4 + j)*512 + h*64 + lane*2;
        k[j] = *(const float2*)r;
        v[j] = *(const float2*)(r + 256);
    }
    float sc[4];
#pragma unroll
    for (int kk = 0; kk < 4; kk++) sc[kk] = q.x*k[kk].x + q.y*k[kk].y;
#pragma unroll
    for (int o = 16; o; o >>= 1)
#pragma unroll
        for (int kk = 0; kk < 4; kk++)
            sc[kk] += __shfl_xor_sync(0xffffffffu, sc[kk], o);
    float mx = -1e30f;
#pragma unroll
    for (int kk = 0; kk < 4; kk++) { sc[kk] *= 0.125f; mx = fmaxf(mx, sc[kk]); }
    float sum = 0.f; float p[4];
#pragma unroll
    for (int kk = 0; kk < 4; kk++) { p[kk] = expf(sc[kk] - mx); sum += p[kk]; }
    float inv = 1.f / sum;
    float2 o2 = make_float2(0.f, 0.f);
#pragma unroll
    for (int kk = 0; kk < 4; kk++) { o2.x = fmaf(p[kk]*inv, v[kk].x, o2.x); o2.y = fmaf(p[kk]*inv, v[kk].y, o2.y); }
    *(float2*)(g_arena + OFF_CUR + (size_t)seq*256 + h*64 + lane*2) = o2;
}

// ---------------- delta helpers ----------------
__global__ void wsum_kernel(const float* __restrict__ dw)
{
    int e = blockIdx.x * 256 + threadIdx.x;
    int d = e >> 8, k = e & 255;
    g_arena[OFF_WS + e] = dw[d*512 + k] + dw[d*512 + 256 + k];
}
// write cur[b][0] rows into BOTH u[b][0] and ct[b][0]
__global__ void copy_s0_both()
{
    int e = blockIdx.x * 256 + threadIdx.x;   // 131072
    int d = e & 255, p = (e >> 8) & 63, b = e >> 14;
    size_t off = ((size_t)(b*2048 + p))*256 + d;
    float v = g_arena[OFF_CUR + off];
    g_arena[OFF_U  + off] = v;
    g_arena[OFF_CT + off] = v;
}
// copy z (depth-3, final for s<=3) for s=1..3 from CT into U
__global__ void copy_z13()
{
    int e = blockIdx.x * 256 + threadIdx.x;   // 393216
    int b = e / 49152, l = e - b*49152;
    size_t off = (size_t)b * (2048*256) + 16384 + l;
    g_arena[OFF_U + off] = g_arena[OFF_CT + off];
}
__global__ void transpose_w2(const float* __restrict__ dw)
{
    int n = blockIdx.x, k = threadIdx.x;
    g_arena[OFF_N1 + (size_t)n*256 + k] = dw[(size_t)k*512 + 256 + n];
}

// ---------------- VQ ----------------
__global__ void cc_kernel(const float* __restrict__ cb)
{
    int row = blockIdx.x, t = threadIdx.x;
    float v = cb[row*256 + t];
    __shared__ float red[256];
    red[t] = v*v; __syncthreads();
    for (int o = 128; o; o >>= 1) { if (t < o) red[t] += red[t+o]; __syncthreads(); }
    if (t == 0) g_arena[OFF_CC + row] = red[0];
}
__global__ __launch_bounds__(256) void argmin_kernel()
{
    int row = blockIdx.x, t = threadIdx.x;
    float x = g_arena[OFF_U + (size_t)row*256 + t];
    __shared__ float red[256];
    red[t] = x*x; __syncthreads();
    for (int o = 128; o; o >>= 1) { if (t < o) red[t] += red[t+o]; __syncthreads(); }
    float xx = red[0];
    __syncthreads();
    const float* dot = g_arena + OFF_DOT + (size_t)row*1024;
    float best = 3.4e38f; int bi = 0;
    for (int j = t; j < 1024; j += 256) {
        float dist = xx - 2.f*dot[j] + g_arena[OFF_CC + j];
        if (dist < best) { best = dist; bi = j; }
    }
    __shared__ float rv[256];
    __shared__ int   ri[256];
    rv[t] = best; ri[t] = bi; __syncthreads();
    for (int o = 128; o; o >>= 1) {
        if (t < o) {
            float v2 = rv[t+o]; int i2 = ri[t+o];
            if (v2 < rv[t] || (v2 == rv[t] && i2 < ri[t])) { rv[t] = v2; ri[t] = i2; }
        }
        __syncthreads();
    }
    if (t == 0) {
        g_idx[row] = ri[0];
        g_arena[OFF_RD + row] = rv[0];   // = sum((ct-q)^2) for this row
    }
}

// ---------------- merged outputs: recon | idx | losses ----------------
__global__ void outputs_kernel(float* __restrict__ out)
{
    int blk = blockIdx.x, t = threadIdx.x;
    if (blk < 4096) {
        int e = blk*256 + t;
        out[e] = g_arena[OFF_LUT + g_idx[e >> 6]*64 + (e & 63)];
    } else if (blk < 4160) {
        int r = (blk - 4096)*256 + t;
        out[1048576 + r] = (float)g_idx[r];
    } else {
        float acc = 0.f;
        for (int k = 0; k < 64; k++)
            acc += g_arena[OFF_RD + t + 256*k];
        __shared__ float red[256];
        red[t] = acc; __syncthreads();
        for (int o = 128; o; o >>= 1) { if (t < o) red[t] += red[t+o]; __syncthreads(); }
        if (t == 0) {
            float mse = red[0] / 4194304.f;
            out[1064960] = 0.25f * mse;
            out[1064961] = mse;
            out[1064962] = 1.25f * mse;
        }
    }
}

#define GEMM(grid, Aext,aOff,lda,aB, Bext,bOff,ldb, bias, cOff,ldc,cB, dOff, M,N,K, epi,alpha,relu) \
    mma_gemm<<<grid,128>>>(Aext,aOff,lda,aB, Bext,bOff,ldb, bias, cOff,ldc,cB, dOff, M,N,K, epi,alpha,relu)
#define GEMMS(st, grid, Aext,aOff,lda,aB, Bext,bOff,ldb, bias, cOff,ldc,cB, dOff, M,N,K, epi,alpha,relu) \
    mma_gemm<<<grid,128,0,st>>>(Aext,aOff,lda,aB, Bext,bOff,ldb, bias, cOff,ldc,cB, dOff, M,N,K, epi,alpha,relu)

// ---------------- orchestration: R15 schedule + stride-8 scan (main-stream only) ----------------
extern "C" void kernel_launch(void* const* d_in, const int* in_sizes, int n_in,
                              void* d_out, int out_size)
{
    const float* obs      = (const float*)d_in[0];
    const float* patch_w  = (const float*)d_in[2];
    const float* patch_b  = (const float*)d_in[3];
    const float* pos      = (const float*)d_in[4];
    const float* sa_qkv_w = (const float*)d_in[5];
    const float* sa_qkv_b = (const float*)d_in[6];
    const float* sa_out_w = (const float*)d_in[7];
    const float* sa_out_b = (const float*)d_in[8];
    const float* sa_ln_g  = (const float*)d_in[9];
    const float* sa_ln_b  = (const float*)d_in[10];
    const float* cqkv_w   = (const float*)d_in[11];
    const float* cqkv_b   = (const float*)d_in[12];
    const float* cout_w   = (const float*)d_in[13];
    const float* cout_b   = (const float*)d_in[14];
    const float* cff1_w   = (const float*)d_in[15];
    const float* cff1_b   = (const float*)d_in[16];
    const float* cff2_w   = (const float*)d_in[17];
    const float* cff2_b   = (const float*)d_in[18];
    const float* cln1_g   = (const float*)d_in[19];
    const float* cln1_b   = (const float*)d_in[20];
    const float* cln2_g   = (const float*)d_in[21];
    const float* cln2_b   = (const float*)d_in[22];
    const float* delta_w  = (const float*)d_in[23];
    const float* delta_b  = (const float*)d_in[24];
    const float* codebook = (const float*)d_in[25];
    const float* dec_w1   = (const float*)d_in[26];
    const float* dec_b1   = (const float*)d_in[27];
    const float* dec_w2   = (const float*)d_in[28];
    const float* dec_b2   = (const float*)d_in[29];
    const float* dec_w3   = (const float*)d_in[30];
    const float* dec_b3   = (const float*)d_in[31];
    float* out = (float*)d_out;
    const long long BSTRIDE = 2048LL*256;

    // side stream + events (coarse fork/join only)
    cudaStream_t s2;
    cudaStreamCreateWithFlags(&s2, cudaStreamNonBlocking);
    cudaEvent_t ev0, evA, evB, evC;
    cudaEventCreateWithFlags(&ev0, cudaEventDisableTiming);
    cudaEventCreateWithFlags(&evA, cudaEventDisableTiming);
    cudaEventCreateWithFlags(&evB, cudaEventDisableTiming);
    cudaEventCreateWithFlags(&evC, cudaEventDisableTiming);

    // ---- fork: side stream does ALL input-only work ----
    cudaEventRecord(ev0, 0);
    cudaStreamWaitEvent(s2, ev0, 0);
    GEMMS(s2, dim3(6,1), pos,0,256,0, sa_qkv_w,0,256, nullptr, OFF_QKVP,768,0, 0, 64,768,256, 0,1.f,0);
    cudaEventRecord(evA, s2);
    // scan constants: ws, N1=W2^T, W2^2..W2^8
    wsum_kernel<<<256,256,0,s2>>>(delta_w);
    transpose_w2<<<256,256,0,s2>>>(delta_w);
    GEMMS(s2, dim3(2,2), delta_w+256,0,512,0, nullptr,OFF_N1,256, nullptr, OFF_M2,256,0, 0, 256,256,256, 0,1.f,0);
    GEMMS(s2, dim3(2,2), nullptr,OFF_M2,256,0, nullptr,OFF_N1,256, nullptr, OFF_M3,256,0, 0, 256,256,256, 0,1.f,0);
    GEMMS(s2, dim3(2,2), nullptr,OFF_M3,256,0, nullptr,OFF_N1,256, nullptr, OFF_M4,256,0, 0, 256,256,256, 0,1.f,0);
    GEMMS(s2, dim3(2,2), nullptr,OFF_M4,256,0, nullptr,OFF_N1,256, nullptr, OFF_M5,256,0, 0, 256,256,256, 0,1.f,0);
    GEMMS(s2, dim3(2,2), nullptr,OFF_M5,256,0, nullptr,OFF_N1,256, nullptr, OFF_M6,256,0, 0, 256,256,256, 0,1.f,0);
    GEMMS(s2, dim3(2,2), nullptr,OFF_M6,256,0, nullptr,OFF_N1,256, nullptr, OFF_M7,256,0, 0, 256,256,256, 0,1.f,0);
    GEMMS(s2, dim3(2,2), nullptr,OFF_M7,256,0, nullptr,OFF_N1,256, nullptr, OFF_M8,256,0, 0, 256,256,256, 0,1.f,0);
    cudaEventRecord(evB, s2);
    // VQ codebook norms + decoder LUT chain
    cc_kernel<<<1024,256,0,s2>>>(codebook);
    GEMMS(s2, dim3(8,8), codebook,0,256,0, dec_w1,0,256, dec_b1, OFF_DH1,1024,0, 0, 1024,1024,256, 0,1.f,1);
    GEMMS(s2, dim3(8,8), nullptr,OFF_DH1,1024,0, dec_w2,0,1024, dec_b2, OFF_DH2,1024,0, 0, 1024,1024,1024, 0,1.f,1);
    GEMMS(s2, dim3(1,8), nullptr,OFF_DH2,1024,0, dec_w3,0,1024, dec_b3, OFF_LUT,64,0, 0, 1024,64,1024, 0,1.f,0);
    cudaEventRecord(evC, s2);

    // ---- main pipeline ----
    GEMM(dim3(2,2), obs,0,64,0, patch_w,0,64, patch_b, OFF_BASE,256,0, 0, 256,256,64, 0,1.f,0);
    tok_kernel<<<16384,256>>>(pos);
    GEMM(dim3(6,2), nullptr,OFF_BASE,256,0, sa_qkv_w,0,256, sa_qkv_b, OFF_QKVB,768,0, 0, 256,768,256, 0,1.f,0);
    cudaStreamWaitEvent(0, evA, 0);
    sa_attn<<<1024,256>>>();
    GEMM(dim3(2,128), nullptr,OFF_ATTN,256,0, sa_out_w,0,256, sa_out_b, OFF_BUF,256,0, 0, 16384,256,256, 0,1.f,0);
    ln_kernel<<<16384,256>>>(OFF_BUF,256, OFF_TOK,256, sa_ln_g, sa_ln_b, OFF_TOK,256);
    // ctx layer 0
    GEMM(dim3(6,128), nullptr,OFF_TOK,256,0, cqkv_w,0,256, cqkv_b, OFF_QKV,768,0, 0, 16384,768,256, 0,1.f,0);
    ctx_attn0<<<8192,256>>>(cqkv_b);
    GEMM(dim3(2,512), nullptr,OFF_ATTN,256,0, cout_w,0,256, cout_b, OFF_BUF,256,0, 0, 65536,256,256, 0,1.f,0);
    ln_kernel<<<65536,256>>>(OFF_BUF,256, 0,-2, cln1_g, cln1_b, OFF_XC,256);
    GEMM(dim3(8,512), nullptr,OFF_XC,256,0, cff1_w,0,256, cff1_b, OFF_H,1024,0, 0, 65536,1024,256, 0,1.f,1);
    GEMM(dim3(2,512), nullptr,OFF_H,1024,0, cff2_w,0,1024, cff2_b, OFF_BUF,256,0, 0, 65536,256,1024, 0,1.f,0);
    ln_kernel<<<65536,256>>>(OFF_BUF,256, OFF_XC,256, cln2_g, cln2_b, OFF_XC,256);
    // ctx layer 1
    GEMM(dim3(4,512), nullptr,OFF_XC,256,0, cqkv_w+768*256+256*256,0,256, cqkv_b+768+256, OFF_KV,512,0, 0, 65536,512,256, 0,1.f,0);
    GEMM(dim3(2,128), nullptr,OFF_XC+768,1024,0, cqkv_w+768*256,0,256, cqkv_b+768, OFF_QB1,256,0, 0, 16384,256,256, 0,1.f,0);
    ctx_attn1<<<8192,256>>>();
    GEMM(dim3(2,128), nullptr,OFF_CUR,256,0, cout_w+256*256,0,256, cout_b+256, OFF_BUF,256,0, 0, 16384,256,256, 0,1.f,0);
    ln_kernel<<<16384,256>>>(OFF_BUF,256, OFF_XC+768,1024, cln1_g+256, cln1_b+256, OFF_CUR,256);
    GEMM(dim3(8,128), nullptr,OFF_CUR,256,0, cff1_w+1024*256,0,256, cff1_b+1024, OFF_H,1024,0, 0, 16384,1024,256, 0,1.f,1);
    GEMM(dim3(2,128), nullptr,OFF_H,1024,0, cff2_w+256*1024,0,1024, cff2_b+256, OFF_BUF,256,0, 0, 16384,256,1024, 0,1.f,0);
    ln_kernel<<<16384,256>>>(OFF_CUR,256, OFF_BUF,256, cln2_g+256, cln2_b+256, OFF_CUR,256);
    // ---- delta scan (stride-8, main stream only) ----
    cudaStreamWaitEvent(0, evB, 0);
    GEMM(dim3(2,128), nullptr,OFF_CUR,256,0, nullptr,OFF_WS,256, delta_b, OFF_U,256,0, 0, 16384,256,256, 0,1.f,0);
    copy_s0_both<<<512,256>>>();
    // depth-3 prefix z into CT (s=1..31)
    GEMM(dim3(2,16,8), nullptr,OFF_U,256,BSTRIDE, delta_w+256,0,512, nullptr, OFF_CT+16384,256,BSTRIDE, OFF_U+16384, 1984,256,256, 2,-1.f,0);
    GEMM(dim3(2,15,8), nullptr,OFF_U,256,BSTRIDE, nullptr,OFF_M2,256, nullptr, OFF_CT+32768,256,BSTRIDE, 0, 1920,256,256, 1, 1.f,0);
    GEMM(dim3(2,15,8), nullptr,OFF_U,256,BSTRIDE, nullptr,OFF_M3,256, nullptr, OFF_CT+49152,256,BSTRIDE, 0, 1856,256,256, 1,-1.f,0);
    // depth-7 prefix z2 into U (s=4..31): U_s = CT_s + CT_{s-4}*M4^T  (reads CT only, writes U — no race)
    GEMM(dim3(2,14,8), nullptr,OFF_CT,256,BSTRIDE, nullptr,OFF_M4,256, nullptr, OFF_U+65536,256,BSTRIDE, OFF_CT+65536, 1792,256,256, 2,1.f,0);
    copy_z13<<<1536,256>>>();   // U_s = CT_s for s=1..3 (final); U_0 already = cur0
    // stride-8 sequential: U[8G..8G+7] += U[8(G-1)..]*M8^T   (3 steps)
    for (int g = 1; g <= 3; g++)
        GEMM(dim3(2,4,8), nullptr,OFF_U+(g-1)*131072LL,256,BSTRIDE, nullptr,OFF_M8,256, nullptr, OFF_U+g*131072LL,256,BSTRIDE, 0, 512,256,256, 1,1.f,0);
    // ---- VQ (ct now lives in U) ----
    GEMM(dim3(8,128), nullptr,OFF_U,256,0, codebook,0,256, nullptr, OFF_DOT,1024,0, 0, 16384,1024,256, 0,1.f,0);
    cudaStreamWaitEvent(0, evC, 0);
    argmin_kernel<<<16384,256>>>();
    // ---- merged outputs ----
    outputs_kernel<<<4161,256>>>(out);

    cudaEventDestroy(ev0);
    cudaEventDestroy(evA);
    cudaEventDestroy(evB);
    cudaEventDestroy(evC);
    cudaStreamDestroy(s2);
}